// round 8
// baseline (speedup 1.0000x reference)
#include <cuda_runtime.h>
#include <math.h>

#define NNODES 50000
#define DEGC 16
#define RECS 208   // record stride (floats): y[128] z[64] el[2] er[2] xg2[2] xg1[2]

// ---------------- scratch (device globals) ---------------------------------
__device__ float g_rec[NNODES * RECS];
__device__ float g_gy[NNODES * 64];     // gate-weighted attn contribution (merge space)
__device__ float g_xm[NNODES * 64];     // x @ Wmerge[0:128]
__device__ float g_vlr[128 * 4];        // [k][el0,el1,er0,er1]
__device__ float g_U[2 * 128 * 64];     // U_h = Wfc_h @ Wmerge2_h

__device__ __forceinline__ float sigmoidf_(float v) { return 1.f / (1.f + __expf(-v)); }

__device__ __forceinline__ unsigned f2tf(float v) {
    unsigned r;
    asm("cvt.rna.tf32.f32 %0, %1;" : "=r"(r) : "f"(v));
    return r;
}

__device__ __forceinline__ void mma_tf32(float c[4], unsigned a0, unsigned a1,
                                         unsigned a2, unsigned a3,
                                         unsigned b0, unsigned b1) {
    asm volatile(
        "mma.sync.aligned.m16n8k8.row.col.f32.tf32.tf32.f32 "
        "{%0,%1,%2,%3}, {%4,%5,%6,%7}, {%8,%9}, {%0,%1,%2,%3};"
        : "+f"(c[0]), "+f"(c[1]), "+f"(c[2]), "+f"(c[3])
        : "r"(a0), "r"(a1), "r"(a2), "r"(a3), "r"(b0), "r"(b1));
}

#define AS_STRIDE 140
#define BS_STRIDE 72
#define MS_STRIDE 76
#define K1_SMEM ((128 * AS_STRIDE + 128 * BS_STRIDE) * 4)  // 108544 B
#define K3_SMEM ((64 * MS_STRIDE * 3 + 64 * BS_STRIDE) * 4) // 76800 B

// ---------------- K0a: fold attn vectors -----------------------------------
__global__ void k0_fold_attn(const float* __restrict__ Wfc,
                             const float* __restrict__ al,
                             const float* __restrict__ ar) {
    int k = threadIdx.x;  // 128
#pragma unroll
    for (int h = 0; h < 2; ++h) {
        float sl = 0.f, sr = 0.f;
#pragma unroll 8
        for (int q = 0; q < 64; ++q) {
            float w = Wfc[k * 128 + h * 64 + q];
            sl += w * al[h * 64 + q];
            sr += w * ar[h * 64 + q];
        }
        g_vlr[k * 4 + h] = sl;
        g_vlr[k * 4 + 2 + h] = sr;
    }
}

// ---------------- K0b: U_h = Wfc_h @ Wmerge2_h -----------------------------
__global__ void k0_fold_U(const float* __restrict__ Wfc,
                          const float* __restrict__ Wmerge) {
    int k = blockIdx.x, h = blockIdx.y, c = threadIdx.x;
    float s = 0.f;
#pragma unroll 8
    for (int q = 0; q < 64; ++q)
        s += Wfc[k * 128 + h * 64 + q] * Wmerge[(128 + h * 64 + q) * 64 + c];
    g_U[(h * 128 + k) * 64 + c] = s;
}

// ---------------- K1: 128-node tile: z | y0 | y1 | xm + scalar tail --------
__global__ __launch_bounds__(256) void k1_node_linear(
    const float* __restrict__ x, const float* __restrict__ Wm,
    const float* __restrict__ bm, const float* __restrict__ Wg,
    const float* __restrict__ Wmerge) {
    extern __shared__ float sm[];
    float(*xs)[AS_STRIDE] = (float(*)[AS_STRIDE])sm;                 // [128][140]
    float(*Bs)[BS_STRIDE] = (float(*)[BS_STRIDE])(sm + 128 * AS_STRIDE);
    const int tid = threadIdx.x, lane = tid & 31, wid = tid >> 5;
    const int n0 = blockIdx.x * 128;
    const int row0 = wid * 16 + (lane >> 2);   // 8 warps x 16 rows = 128
    const int kq = lane & 3;
    const int cn = lane >> 2;
    const int node0 = n0 + row0, node1 = node0 + 8;

    for (int idx = tid; idx < 128 * 128; idx += 256) {
        int nn = idx >> 7, k = idx & 127;
        int node = n0 + nn;
        float v = (node < NNODES) ? x[node * 128 + k] : 0.f;
        xs[nn][k] = __uint_as_float(f2tf(v));
    }

    // passes: 0 -> z (Wm,+bm -> rec+128), 1 -> y0 (U0 -> rec+0),
    //         2 -> y1 (U1 -> rec+64),     3 -> xm (Wmerge[0:128] -> g_xm)
    for (int pass = 0; pass < 4; ++pass) {
        __syncthreads();
        for (int idx = tid; idx < 128 * 64; idx += 256) {
            int k = idx >> 6, c = idx & 63;
            float w;
            if (pass == 0) w = Wm[k * 64 + c];
            else if (pass == 3) w = Wmerge[k * 64 + c];
            else w = g_U[((pass - 1) * 128 + k) * 64 + c];
            Bs[k][c] = __uint_as_float(f2tf(w));
        }
        __syncthreads();

        float C[8][4];
#pragma unroll
        for (int nt = 0; nt < 8; ++nt)
#pragma unroll
            for (int e = 0; e < 4; ++e) C[nt][e] = 0.f;

#pragma unroll
        for (int ks = 0; ks < 16; ++ks) {
            int kb = ks * 8;
            unsigned a0 = __float_as_uint(xs[row0][kb + kq]);
            unsigned a1 = __float_as_uint(xs[row0 + 8][kb + kq]);
            unsigned a2 = __float_as_uint(xs[row0][kb + kq + 4]);
            unsigned a3 = __float_as_uint(xs[row0 + 8][kb + kq + 4]);
#pragma unroll
            for (int nt = 0; nt < 8; ++nt) {
                int col = nt * 8 + cn;
                unsigned b0 = __float_as_uint(Bs[kb + kq][col]);
                unsigned b1 = __float_as_uint(Bs[kb + kq + 4][col]);
                mma_tf32(C[nt], a0, a1, a2, a3, b0, b1);
            }
        }

        if (pass == 3) {
#pragma unroll
            for (int nt = 0; nt < 8; ++nt) {
                int c0 = nt * 8 + (lane & 3) * 2;
                if (node0 < NNODES)
                    *(float2*)&g_xm[(size_t)node0 * 64 + c0] = make_float2(C[nt][0], C[nt][1]);
                if (node1 < NNODES)
                    *(float2*)&g_xm[(size_t)node1 * 64 + c0] = make_float2(C[nt][2], C[nt][3]);
            }
        } else {
            int cbase = (pass == 0) ? 128 : (pass - 1) * 64;
#pragma unroll
            for (int nt = 0; nt < 8; ++nt) {
                int c0 = nt * 8 + (lane & 3) * 2;
                float ba = 0.f, bb = 0.f;
                if (pass == 0) { ba = bm[c0]; bb = bm[c0 + 1]; }
                if (node0 < NNODES)
                    *(float2*)&g_rec[(size_t)node0 * RECS + cbase + c0] =
                        make_float2(C[nt][0] + ba, C[nt][1] + bb);
                if (node1 < NNODES)
                    *(float2*)&g_rec[(size_t)node1 * RECS + cbase + c0] =
                        make_float2(C[nt][2] + ba, C[nt][3] + bb);
            }
        }
    }

    // tail: 8 scalars per node: el0,el1,er0,er1,xg2_0,xg2_1,xg1_0,xg1_1
    __syncthreads();
    float* vs = (float*)Bs;  // [128][8]
    for (int idx = tid; idx < 128 * 8; idx += 256) {
        int k = idx >> 3, c = idx & 7;
        float v;
        if (c < 4) v = g_vlr[k * 4 + c];
        else if (c < 6) v = Wg[(128 + k) * 2 + (c - 4)];
        else v = Wg[k * 2 + (c - 6)];
        vs[idx] = v;
    }
    __syncthreads();
#pragma unroll
    for (int w = 0; w < 4; ++w) {
        int it = tid + w * 256;
        int nn = it >> 3, c = it & 7;
        float s = 0.f;
#pragma unroll 16
        for (int k = 0; k < 128; ++k) s += xs[nn][k] * vs[k * 8 + c];
        int node = n0 + nn;
        if (node < NNODES) g_rec[(size_t)node * RECS + 192 + c] = s;
    }
}

// ---------------- K2: one warp per node, zero barriers ---------------------
__global__ __launch_bounds__(256) void k2_aggregate(
    const int* __restrict__ src, const float* __restrict__ Wg,
    const float* __restrict__ bg) {
    const unsigned FULL = 0xffffffffu;
    const int n = blockIdx.x * 8 + ((threadIdx.x) >> 5);
    if (n >= NNODES) return;
    const int lane = threadIdx.x & 31;
    const int j16 = lane & 15, h = lane >> 4;

    int srcj = src[n * DEGC + j16];

    // ---- e + softmax per head (16-lane butterfly groups) ----
    float el = g_rec[(size_t)srcj * RECS + 192 + h];
    float er = g_rec[(size_t)n * RECS + 194 + h];
    float e = el + er;
    e = (e > 0.f) ? e : 0.2f * e;
    float m = e;
#pragma unroll
    for (int o = 8; o > 0; o >>= 1) m = fmaxf(m, __shfl_xor_sync(FULL, m, o));
    float ee = __expf(e - m);
    float s = ee;
#pragma unroll
    for (int o = 8; o > 0; o >>= 1) s += __shfl_xor_sync(FULL, s, o);
    float alpha = ee / fmaxf(s, 1e-12f);

    // ---- xg2 mean term ----
    float xg2 = g_rec[(size_t)srcj * RECS + 196 + h];
#pragma unroll
    for (int o = 8; o > 0; o >>= 1) xg2 += __shfl_xor_sync(FULL, xg2, o);

    // ---- z max: lane owns z cols 2*lane, 2*lane+1 ----
    float mz0 = -3.4e38f, mz1 = -3.4e38f;
#pragma unroll
    for (int j = 0; j < 16; ++j) {
        int sj = __shfl_sync(FULL, srcj, j);
        float2 z2 = *(const float2*)&g_rec[(size_t)sj * RECS + 128 + 2 * lane];
        mz0 = fmaxf(mz0, z2.x);
        mz1 = fmaxf(mz1, z2.y);
    }
    float p0 = mz0 * Wg[(256 + 2 * lane) * 2 + 0] + mz1 * Wg[(256 + 2 * lane + 1) * 2 + 0];
    float p1 = mz0 * Wg[(256 + 2 * lane) * 2 + 1] + mz1 * Wg[(256 + 2 * lane + 1) * 2 + 1];
#pragma unroll
    for (int o = 16; o > 0; o >>= 1) {
        p0 += __shfl_xor_sync(FULL, p0, o);
        p1 += __shfl_xor_sync(FULL, p1, o);
    }
    float g3 = (h == 0) ? p0 : p1;
    float xg1 = g_rec[(size_t)n * RECS + 198 + h];
    float gate = sigmoidf_(xg1 + 0.0625f * xg2 + g3 + bg[h]);

    // ---- alpha-weighted y: lane owns cols 4L..4L+3 (head = L>>4) ----------
    float4 acc = make_float4(0.f, 0.f, 0.f, 0.f);
#pragma unroll
    for (int j = 0; j < 16; ++j) {
        int sj = __shfl_sync(FULL, srcj, j);
        float a = __shfl_sync(FULL, alpha, (lane & 16) | j);
        float4 y4 = *(const float4*)&g_rec[(size_t)sj * RECS + 4 * lane];
        acc.x += a * y4.x; acc.y += a * y4.y; acc.z += a * y4.z; acc.w += a * y4.w;
    }

    float got = __shfl_xor_sync(FULL, gate, 16);
    float ox = __shfl_xor_sync(FULL, acc.x, 16);
    float oy = __shfl_xor_sync(FULL, acc.y, 16);
    float oz = __shfl_xor_sync(FULL, acc.z, 16);
    float ow = __shfl_xor_sync(FULL, acc.w, 16);
    if (lane < 16) {
        float4 gy;
        gy.x = gate * acc.x + got * ox;
        gy.y = gate * acc.y + got * oy;
        gy.z = gate * acc.z + got * oz;
        gy.w = gate * acc.w + got * ow;
        *(float4*)&g_gy[(size_t)n * 64 + 4 * lane] = gy;
    }
}

// ---------------- K3 fused: meso = xm + gy + bmerge ; GRU ; out ------------
__global__ __launch_bounds__(256) void k3_fused(
    const float* __restrict__ bmerge,
    const float* __restrict__ hin, const float* __restrict__ W_ih,
    const float* __restrict__ W_hh, const float* __restrict__ b_ih,
    const float* __restrict__ b_hh, const float* __restrict__ Wout,
    const float* __restrict__ bout, float* __restrict__ out) {
    extern __shared__ float sm[];
    float(*ms)[MS_STRIDE] = (float(*)[MS_STRIDE])sm;
    float(*hs)[MS_STRIDE] = (float(*)[MS_STRIDE])(sm + 64 * MS_STRIDE);
    float(*nh)[MS_STRIDE] = (float(*)[MS_STRIDE])(sm + 2 * 64 * MS_STRIDE);
    float(*wt)[BS_STRIDE] = (float(*)[BS_STRIDE])(sm + 3 * 64 * MS_STRIDE);

    const int tid = threadIdx.x, lane = tid & 31, wid = tid >> 5;
    const int n0 = blockIdx.x * 64;
    const int row0 = (wid >> 1) * 16 + (lane >> 2);
    const int colh = (wid & 1) * 32;
    const int kq = lane & 3;
    const int cn = lane >> 2;
    const int node0 = n0 + row0, node1 = node0 + 8;

    // stage A: meso = xm + gy + bmerge (elementwise) ; load h tile
    for (int idx = tid; idx < 64 * 64; idx += 256) {
        int nn = idx >> 6, k = idx & 63;
        int node = n0 + nn;
        float mv = 0.f, hv = 0.f;
        if (node < NNODES) {
            mv = g_xm[(size_t)node * 64 + k] + g_gy[(size_t)node * 64 + k] + bmerge[k];
            hv = hin[node * 64 + k];
        }
        ms[nn][k] = __uint_as_float(f2tf(mv));
        hs[nn][k] = hv;
    }

    // stage B: GRU
    float rr[4][4], zz[4][4];
    for (int g = 0; g < 3; ++g) {
        float ai[4][4], ah[4][4];
        __syncthreads();
        for (int idx = tid; idx < 64 * 64; idx += 256) {
            int c = idx >> 6, k = idx & 63;
            wt[k][c] = __uint_as_float(f2tf(W_ih[(g * 64 + c) * 64 + k]));
        }
        __syncthreads();
#pragma unroll
        for (int nt = 0; nt < 4; ++nt)
#pragma unroll
            for (int e = 0; e < 4; ++e) ai[nt][e] = 0.f;
#pragma unroll
        for (int ks = 0; ks < 8; ++ks) {
            int kb = ks * 8;
            unsigned a0 = __float_as_uint(ms[row0][kb + kq]);
            unsigned a1 = __float_as_uint(ms[row0 + 8][kb + kq]);
            unsigned a2 = __float_as_uint(ms[row0][kb + kq + 4]);
            unsigned a3 = __float_as_uint(ms[row0 + 8][kb + kq + 4]);
#pragma unroll
            for (int nt = 0; nt < 4; ++nt) {
                int col = colh + nt * 8 + cn;
                unsigned b0 = __float_as_uint(wt[kb + kq][col]);
                unsigned b1 = __float_as_uint(wt[kb + kq + 4][col]);
                mma_tf32(ai[nt], a0, a1, a2, a3, b0, b1);
            }
        }
        __syncthreads();
        for (int idx = tid; idx < 64 * 64; idx += 256) {
            int c = idx >> 6, k = idx & 63;
            wt[k][c] = __uint_as_float(f2tf(W_hh[(g * 64 + c) * 64 + k]));
        }
        __syncthreads();
#pragma unroll
        for (int nt = 0; nt < 4; ++nt)
#pragma unroll
            for (int e = 0; e < 4; ++e) ah[nt][e] = 0.f;
#pragma unroll
        for (int ks = 0; ks < 8; ++ks) {
            int kb = ks * 8;
            unsigned h0 = __float_as_uint(hs[row0][kb + kq]);
            unsigned h1 = __float_as_uint(hs[row0 + 8][kb + kq]);
            unsigned h2 = __float_as_uint(hs[row0][kb + kq + 4]);
            unsigned h3 = __float_as_uint(hs[row0 + 8][kb + kq + 4]);
#pragma unroll
            for (int nt = 0; nt < 4; ++nt) {
                int col = colh + nt * 8 + cn;
                unsigned b0 = __float_as_uint(wt[kb + kq][col]);
                unsigned b1 = __float_as_uint(wt[kb + kq + 4][col]);
                mma_tf32(ah[nt], h0, h1, h2, h3, b0, b1);
            }
        }

#pragma unroll
        for (int nt = 0; nt < 4; ++nt) {
#pragma unroll
            for (int e = 0; e < 4; ++e) {
                int c = colh + nt * 8 + (lane & 3) * 2 + (e & 1);
                int r = row0 + (e >> 1) * 8;
                float gi = ai[nt][e] + b_ih[g * 64 + c];
                float gh = ah[nt][e] + b_hh[g * 64 + c];
                if (g == 0) {
                    rr[nt][e] = sigmoidf_(gi + gh);
                } else if (g == 1) {
                    zz[nt][e] = sigmoidf_(gi + gh);
                } else {
                    float ng = tanhf(gi + rr[nt][e] * gh);
                    float hv = hs[r][c];
                    float v = (1.f - zz[nt][e]) * ng + zz[nt][e] * hv;
                    int node = n0 + r;
                    if (node < NNODES)
                        out[(size_t)NNODES * 64 + (size_t)node * 64 + c] = v;
                    nh[r][c] = __uint_as_float(f2tf(v));
                }
            }
        }
    }

    // output projection
    __syncthreads();
    for (int idx = tid; idx < 64 * 64; idx += 256) {
        int k = idx >> 6, c = idx & 63;
        wt[k][c] = __uint_as_float(f2tf(Wout[k * 64 + c]));
    }
    __syncthreads();

    float C[4][4];
#pragma unroll
    for (int nt = 0; nt < 4; ++nt)
#pragma unroll
        for (int e = 0; e < 4; ++e) C[nt][e] = 0.f;
#pragma unroll
    for (int ks = 0; ks < 8; ++ks) {
        int kb = ks * 8;
        unsigned a0 = __float_as_uint(nh[row0][kb + kq]);
        unsigned a1 = __float_as_uint(nh[row0 + 8][kb + kq]);
        unsigned a2 = __float_as_uint(nh[row0][kb + kq + 4]);
        unsigned a3 = __float_as_uint(nh[row0 + 8][kb + kq + 4]);
#pragma unroll
        for (int nt = 0; nt < 4; ++nt) {
            int col = colh + nt * 8 + cn;
            unsigned b0 = __float_as_uint(wt[kb + kq][col]);
            unsigned b1 = __float_as_uint(wt[kb + kq + 4][col]);
            mma_tf32(C[nt], a0, a1, a2, a3, b0, b1);
        }
    }
#pragma unroll
    for (int nt = 0; nt < 4; ++nt) {
        int c0 = colh + nt * 8 + (lane & 3) * 2;
        float ba = bout[c0], bb = bout[c0 + 1];
        if (node0 < NNODES)
            *(float2*)&out[(size_t)node0 * 64 + c0] = make_float2(C[nt][0] + ba, C[nt][1] + bb);
        if (node1 < NNODES)
            *(float2*)&out[(size_t)node1 * 64 + c0] = make_float2(C[nt][2] + ba, C[nt][3] + bb);
    }
}

// ---------------- launch ---------------------------------------------------
extern "C" void kernel_launch(void* const* d_in, const int* in_sizes, int n_in,
                              void* d_out, int out_size) {
    const float* x    = (const float*)d_in[0];
    const float* hin  = (const float*)d_in[1];
    const int*   srcp = (const int*)d_in[2];
    const float* Wm   = (const float*)d_in[4];
    const float* bm   = (const float*)d_in[5];
    const float* Wg   = (const float*)d_in[6];
    const float* bg   = (const float*)d_in[7];
    const float* Wfc  = (const float*)d_in[8];
    const float* al   = (const float*)d_in[9];
    const float* ar   = (const float*)d_in[10];
    const float* Wmg  = (const float*)d_in[11];
    const float* bmg  = (const float*)d_in[12];
    const float* Wih  = (const float*)d_in[13];
    const float* Whh  = (const float*)d_in[14];
    const float* bih  = (const float*)d_in[15];
    const float* bhh  = (const float*)d_in[16];
    const float* Wo   = (const float*)d_in[17];
    const float* bo   = (const float*)d_in[18];
    float* out = (float*)d_out;

    cudaFuncSetAttribute(k1_node_linear, cudaFuncAttributeMaxDynamicSharedMemorySize, K1_SMEM);
    cudaFuncSetAttribute(k3_fused, cudaFuncAttributeMaxDynamicSharedMemorySize, K3_SMEM);

    k0_fold_attn<<<1, 128>>>(Wfc, al, ar);
    k0_fold_U<<<dim3(128, 2), 64>>>(Wfc, Wmg);
    k1_node_linear<<<(NNODES + 127) / 128, 256, K1_SMEM>>>(x, Wm, bm, Wg, Wmg);
    k2_aggregate<<<(NNODES + 7) / 8, 256>>>(srcp, Wg, bg);
    k3_fused<<<(NNODES + 63) / 64, 256, K3_SMEM>>>(bmg, hin, Wih, Whh, bih, bhh, Wo, bo, out);
}

// round 9
// speedup vs baseline: 1.0318x; 1.0318x over previous
#include <cuda_runtime.h>
#include <math.h>

#define NNODES 50000
#define DEGC 16
#define RECS 208   // record: y[128] z[64] el[2] er[2] xg2[2] xg1[2]
#define NTILES 782 // 64-node tiles
#define GRID_P 148 // persistent grid

// ---------------- scratch (device globals) ---------------------------------
__device__ float g_rec[NNODES * RECS];
__device__ float g_gy[NNODES * 64];
__device__ float g_xm[NNODES * 64];
__device__ float g_vlr[128 * 4];
__device__ float g_U[2 * 128 * 64];

__device__ __forceinline__ float sigmoidf_(float v) { return 1.f / (1.f + __expf(-v)); }

__device__ __forceinline__ unsigned f2tf(float v) {
    unsigned r;
    asm("cvt.rna.tf32.f32 %0, %1;" : "=r"(r) : "f"(v));
    return r;
}

__device__ __forceinline__ void mma_tf32(float c[4], unsigned a0, unsigned a1,
                                         unsigned a2, unsigned a3,
                                         unsigned b0, unsigned b1) {
    asm volatile(
        "mma.sync.aligned.m16n8k8.row.col.f32.tf32.tf32.f32 "
        "{%0,%1,%2,%3}, {%4,%5,%6,%7}, {%8,%9}, {%0,%1,%2,%3};"
        : "+f"(c[0]), "+f"(c[1]), "+f"(c[2]), "+f"(c[3])
        : "r"(a0), "r"(a1), "r"(a2), "r"(a3), "r"(b0), "r"(b1));
}

#define XS_STRIDE 140
#define WS_STRIDE 72
#define MS_STRIDE 76
// k1 smem floats: ws 4*128*72=36864 | vs 1024 | xs 64*140=8960  -> 46848 fl = 187392 B
#define K1_SMEM (46848 * 4)
// k3 smem floats: ws7 7*64*72=32256 | ms/hs/nh 3*64*76=14592   -> 46848 fl = 187392 B
#define K3_SMEM (46848 * 4)

// ---------------- K0a: fold attn vectors -----------------------------------
__global__ void k0_fold_attn(const float* __restrict__ Wfc,
                             const float* __restrict__ al,
                             const float* __restrict__ ar) {
    int k = threadIdx.x;  // 128
#pragma unroll
    for (int h = 0; h < 2; ++h) {
        float sl = 0.f, sr = 0.f;
#pragma unroll 8
        for (int q = 0; q < 64; ++q) {
            float w = Wfc[k * 128 + h * 64 + q];
            sl += w * al[h * 64 + q];
            sr += w * ar[h * 64 + q];
        }
        g_vlr[k * 4 + h] = sl;
        g_vlr[k * 4 + 2 + h] = sr;
    }
}

// ---------------- K0b: U_h = Wfc_h @ Wmerge2_h -----------------------------
__global__ void k0_fold_U(const float* __restrict__ Wfc,
                          const float* __restrict__ Wmerge) {
    int k = blockIdx.x, h = blockIdx.y, c = threadIdx.x;
    float s = 0.f;
#pragma unroll 8
    for (int q = 0; q < 64; ++q)
        s += Wfc[k * 128 + h * 64 + q] * Wmerge[(128 + h * 64 + q) * 64 + c];
    g_U[(h * 128 + k) * 64 + c] = s;
}

// ---------------- K1 persistent: weights resident, tile loop ---------------
__global__ __launch_bounds__(256) void k1_node_linear(
    const float* __restrict__ x, const float* __restrict__ Wm,
    const float* __restrict__ bm, const float* __restrict__ Wg,
    const float* __restrict__ Wmerge) {
    extern __shared__ float sm[];
    float* wsm = sm;                                   // [4][128][72]
    float* vs = sm + 4 * 128 * WS_STRIDE;              // [128][8]
    float(*xs)[XS_STRIDE] = (float(*)[XS_STRIDE])(sm + 4 * 128 * WS_STRIDE + 1024);
    const int tid = threadIdx.x, lane = tid & 31, wid = tid >> 5;
    const int row0 = (wid >> 1) * 16 + (lane >> 2);
    const int colh = (wid & 1) * 32;
    const int kq = lane & 3;
    const int cn = lane >> 2;

    // ---- load all weights once ----
    for (int idx = tid; idx < 4 * 128 * 64; idx += 256) {
        int p = idx >> 13, rem = idx & 8191, k = rem >> 6, c = rem & 63;
        float w;
        if (p == 0) w = Wm[k * 64 + c];
        else if (p == 3) w = Wmerge[k * 64 + c];
        else w = g_U[((p - 1) * 128 + k) * 64 + c];
        wsm[p * 128 * WS_STRIDE + k * WS_STRIDE + c] = __uint_as_float(f2tf(w));
    }
    for (int idx = tid; idx < 1024; idx += 256) {
        int k = idx >> 3, c = idx & 7;
        float v;
        if (c < 4) v = g_vlr[k * 4 + c];
        else if (c < 6) v = Wg[(128 + k) * 2 + (c - 4)];
        else v = Wg[k * 2 + (c - 6)];
        vs[idx] = v;
    }

    // ---- first tile load ----
    int t = blockIdx.x;
    {
        int n0 = t * 64;
#pragma unroll
        for (int i = 0; i < 32; ++i) {
            int idx = tid + i * 256, nn = idx >> 7, k = idx & 127;
            int node = n0 + nn;
            xs[nn][k] = __uint_as_float(f2tf((node < NNODES) ? x[node * 128 + k] : 0.f));
        }
    }
    __syncthreads();

    for (;;) {
        const int tn = t + GRID_P;
        const bool hasnext = tn < NTILES;
        float pf[32];
        if (hasnext) {
            int n0n = tn * 64;
#pragma unroll
            for (int i = 0; i < 32; ++i) {
                int idx = tid + i * 256, nn = idx >> 7, k = idx & 127;
                int node = n0n + nn;
                pf[i] = (node < NNODES) ? x[node * 128 + k] : 0.f;
            }
        }

        const int n0 = t * 64;
        const int node0 = n0 + row0, node1 = node0 + 8;

        // 4 GEMM passes, weights resident, no syncs between
#pragma unroll
        for (int pass = 0; pass < 4; ++pass) {
            float(*W)[WS_STRIDE] = (float(*)[WS_STRIDE])(wsm + pass * 128 * WS_STRIDE);
            float C[4][4];
#pragma unroll
            for (int nt = 0; nt < 4; ++nt)
#pragma unroll
                for (int e = 0; e < 4; ++e) C[nt][e] = 0.f;
#pragma unroll
            for (int ks = 0; ks < 16; ++ks) {
                int kb = ks * 8;
                unsigned a0 = __float_as_uint(xs[row0][kb + kq]);
                unsigned a1 = __float_as_uint(xs[row0 + 8][kb + kq]);
                unsigned a2 = __float_as_uint(xs[row0][kb + kq + 4]);
                unsigned a3 = __float_as_uint(xs[row0 + 8][kb + kq + 4]);
#pragma unroll
                for (int nt = 0; nt < 4; ++nt) {
                    int col = colh + nt * 8 + cn;
                    unsigned b0 = __float_as_uint(W[kb + kq][col]);
                    unsigned b1 = __float_as_uint(W[kb + kq + 4][col]);
                    mma_tf32(C[nt], a0, a1, a2, a3, b0, b1);
                }
            }
            if (pass == 3) {
#pragma unroll
                for (int nt = 0; nt < 4; ++nt) {
                    int c0 = colh + nt * 8 + (lane & 3) * 2;
                    if (node0 < NNODES)
                        *(float2*)&g_xm[(size_t)node0 * 64 + c0] = make_float2(C[nt][0], C[nt][1]);
                    if (node1 < NNODES)
                        *(float2*)&g_xm[(size_t)node1 * 64 + c0] = make_float2(C[nt][2], C[nt][3]);
                }
            } else {
                int cbase = (pass == 0) ? 128 : (pass - 1) * 64;
#pragma unroll
                for (int nt = 0; nt < 4; ++nt) {
                    int c0 = colh + nt * 8 + (lane & 3) * 2;
                    float ba = 0.f, bb = 0.f;
                    if (pass == 0) { ba = bm[c0]; bb = bm[c0 + 1]; }
                    if (node0 < NNODES)
                        *(float2*)&g_rec[(size_t)node0 * RECS + cbase + c0] =
                            make_float2(C[nt][0] + ba, C[nt][1] + bb);
                    if (node1 < NNODES)
                        *(float2*)&g_rec[(size_t)node1 * RECS + cbase + c0] =
                            make_float2(C[nt][2] + ba, C[nt][3] + bb);
                }
            }
        }

        // scalar tail: 64 nodes x 8 = 512 items
#pragma unroll
        for (int w = 0; w < 2; ++w) {
            int it = tid + w * 256;
            int nn = it >> 3, c = it & 7;
            float s = 0.f;
#pragma unroll 16
            for (int k = 0; k < 128; ++k) s += xs[nn][k] * vs[k * 8 + c];
            int node = n0 + nn;
            if (node < NNODES) g_rec[(size_t)node * RECS + 192 + c] = s;
        }

        __syncthreads();  // all xs reads done
        if (!hasnext) break;
#pragma unroll
        for (int i = 0; i < 32; ++i) {
            int idx = tid + i * 256, nn = idx >> 7, k = idx & 127;
            xs[nn][k] = __uint_as_float(f2tf(pf[i]));
        }
        t = tn;
        __syncthreads();
    }
}

// ---------------- K2: one warp per node, zero barriers ---------------------
__global__ __launch_bounds__(256) void k2_aggregate(
    const int* __restrict__ src, const float* __restrict__ Wg,
    const float* __restrict__ bg) {
    const unsigned FULL = 0xffffffffu;
    const int n = blockIdx.x * 8 + ((threadIdx.x) >> 5);
    if (n >= NNODES) return;
    const int lane = threadIdx.x & 31;
    const int j16 = lane & 15, h = lane >> 4;

    int srcj = src[n * DEGC + j16];

    float el = g_rec[(size_t)srcj * RECS + 192 + h];
    float er = g_rec[(size_t)n * RECS + 194 + h];
    float e = el + er;
    e = (e > 0.f) ? e : 0.2f * e;
    float m = e;
#pragma unroll
    for (int o = 8; o > 0; o >>= 1) m = fmaxf(m, __shfl_xor_sync(FULL, m, o));
    float ee = __expf(e - m);
    float s = ee;
#pragma unroll
    for (int o = 8; o > 0; o >>= 1) s += __shfl_xor_sync(FULL, s, o);
    float alpha = ee / fmaxf(s, 1e-12f);

    float xg2 = g_rec[(size_t)srcj * RECS + 196 + h];
#pragma unroll
    for (int o = 8; o > 0; o >>= 1) xg2 += __shfl_xor_sync(FULL, xg2, o);

    float mz0 = -3.4e38f, mz1 = -3.4e38f;
#pragma unroll
    for (int j = 0; j < 16; ++j) {
        int sj = __shfl_sync(FULL, srcj, j);
        float2 z2 = *(const float2*)&g_rec[(size_t)sj * RECS + 128 + 2 * lane];
        mz0 = fmaxf(mz0, z2.x);
        mz1 = fmaxf(mz1, z2.y);
    }
    float p0 = mz0 * Wg[(256 + 2 * lane) * 2 + 0] + mz1 * Wg[(256 + 2 * lane + 1) * 2 + 0];
    float p1 = mz0 * Wg[(256 + 2 * lane) * 2 + 1] + mz1 * Wg[(256 + 2 * lane + 1) * 2 + 1];
#pragma unroll
    for (int o = 16; o > 0; o >>= 1) {
        p0 += __shfl_xor_sync(FULL, p0, o);
        p1 += __shfl_xor_sync(FULL, p1, o);
    }
    float g3 = (h == 0) ? p0 : p1;
    float xg1 = g_rec[(size_t)n * RECS + 198 + h];
    float gate = sigmoidf_(xg1 + 0.0625f * xg2 + g3 + bg[h]);

    float4 acc = make_float4(0.f, 0.f, 0.f, 0.f);
#pragma unroll
    for (int j = 0; j < 16; ++j) {
        int sj = __shfl_sync(FULL, srcj, j);
        float a = __shfl_sync(FULL, alpha, (lane & 16) | j);
        float4 y4 = *(const float4*)&g_rec[(size_t)sj * RECS + 4 * lane];
        acc.x += a * y4.x; acc.y += a * y4.y; acc.z += a * y4.z; acc.w += a * y4.w;
    }

    float got = __shfl_xor_sync(FULL, gate, 16);
    float ox = __shfl_xor_sync(FULL, acc.x, 16);
    float oy = __shfl_xor_sync(FULL, acc.y, 16);
    float oz = __shfl_xor_sync(FULL, acc.z, 16);
    float ow = __shfl_xor_sync(FULL, acc.w, 16);
    if (lane < 16) {
        float4 gy;
        gy.x = gate * acc.x + got * ox;
        gy.y = gate * acc.y + got * oy;
        gy.z = gate * acc.z + got * oz;
        gy.w = gate * acc.w + got * ow;
        *(float4*)&g_gy[(size_t)n * 64 + 4 * lane] = gy;
    }
}

// ---------------- K3 persistent: weights resident, GRU + out ---------------
__global__ __launch_bounds__(256) void k3_fused(
    const float* __restrict__ bmerge,
    const float* __restrict__ hin, const float* __restrict__ W_ih,
    const float* __restrict__ W_hh, const float* __restrict__ b_ih,
    const float* __restrict__ b_hh, const float* __restrict__ Wout,
    const float* __restrict__ bout, float* __restrict__ out) {
    extern __shared__ float sm[];
    float* wsm = sm;                                    // [7][64][72]
    float(*ms)[MS_STRIDE] = (float(*)[MS_STRIDE])(sm + 7 * 64 * WS_STRIDE);
    float(*hs)[MS_STRIDE] = (float(*)[MS_STRIDE])(sm + 7 * 64 * WS_STRIDE + 64 * MS_STRIDE);
    float(*nh)[MS_STRIDE] = (float(*)[MS_STRIDE])(sm + 7 * 64 * WS_STRIDE + 2 * 64 * MS_STRIDE);
    const int tid = threadIdx.x, lane = tid & 31, wid = tid >> 5;
    const int row0 = (wid >> 1) * 16 + (lane >> 2);
    const int colh = (wid & 1) * 32;
    const int kq = lane & 3;
    const int cn = lane >> 2;

    // ---- load all weights once: 0..2 W_ih, 3..5 W_hh, 6 Wout ----
    for (int idx = tid; idx < 7 * 64 * 64; idx += 256) {
        int p = idx >> 12, rem = idx & 4095, k = rem >> 6, c = rem & 63;
        float w;
        if (p < 3) w = W_ih[(p * 64 + c) * 64 + k];
        else if (p < 6) w = W_hh[((p - 3) * 64 + c) * 64 + k];
        else w = Wout[k * 64 + c];
        wsm[p * 64 * WS_STRIDE + k * WS_STRIDE + c] = __uint_as_float(f2tf(w));
    }
    __syncthreads();

    for (int t = blockIdx.x; t < NTILES; t += GRID_P) {
        const int n0 = t * 64;
        const int node0 = n0 + row0, node1 = node0 + 8;

        // load ms (= xm + gy + bmerge) and h tile
        for (int idx = tid; idx < 64 * 64; idx += 256) {
            int nn = idx >> 6, k = idx & 63;
            int node = n0 + nn;
            float mv = 0.f, hv = 0.f;
            if (node < NNODES) {
                mv = g_xm[(size_t)node * 64 + k] + g_gy[(size_t)node * 64 + k] + bmerge[k];
                hv = hin[node * 64 + k];
            }
            ms[nn][k] = __uint_as_float(f2tf(mv));
            hs[nn][k] = hv;
        }
        __syncthreads();

        float rr[4][4], zz[4][4];
#pragma unroll
        for (int g = 0; g < 3; ++g) {
            float(*Wi)[WS_STRIDE] = (float(*)[WS_STRIDE])(wsm + g * 64 * WS_STRIDE);
            float(*Wh)[WS_STRIDE] = (float(*)[WS_STRIDE])(wsm + (3 + g) * 64 * WS_STRIDE);
            float ai[4][4], ah[4][4];
#pragma unroll
            for (int nt = 0; nt < 4; ++nt)
#pragma unroll
                for (int e = 0; e < 4; ++e) { ai[nt][e] = 0.f; ah[nt][e] = 0.f; }
#pragma unroll
            for (int ks = 0; ks < 8; ++ks) {
                int kb = ks * 8;
                unsigned a0 = __float_as_uint(ms[row0][kb + kq]);
                unsigned a1 = __float_as_uint(ms[row0 + 8][kb + kq]);
                unsigned a2 = __float_as_uint(ms[row0][kb + kq + 4]);
                unsigned a3 = __float_as_uint(ms[row0 + 8][kb + kq + 4]);
                unsigned h0 = __float_as_uint(hs[row0][kb + kq]);
                unsigned h1 = __float_as_uint(hs[row0 + 8][kb + kq]);
                unsigned h2 = __float_as_uint(hs[row0][kb + kq + 4]);
                unsigned h3 = __float_as_uint(hs[row0 + 8][kb + kq + 4]);
#pragma unroll
                for (int nt = 0; nt < 4; ++nt) {
                    int col = colh + nt * 8 + cn;
                    unsigned bi0 = __float_as_uint(Wi[kb + kq][col]);
                    unsigned bi1 = __float_as_uint(Wi[kb + kq + 4][col]);
                    unsigned bh0 = __float_as_uint(Wh[kb + kq][col]);
                    unsigned bh1 = __float_as_uint(Wh[kb + kq + 4][col]);
                    mma_tf32(ai[nt], a0, a1, a2, a3, bi0, bi1);
                    mma_tf32(ah[nt], h0, h1, h2, h3, bh0, bh1);
                }
            }

#pragma unroll
            for (int nt = 0; nt < 4; ++nt) {
#pragma unroll
                for (int e = 0; e < 4; ++e) {
                    int c = colh + nt * 8 + (lane & 3) * 2 + (e & 1);
                    int r = row0 + (e >> 1) * 8;
                    float gi = ai[nt][e] + b_ih[g * 64 + c];
                    float gh = ah[nt][e] + b_hh[g * 64 + c];
                    if (g == 0) {
                        rr[nt][e] = sigmoidf_(gi + gh);
                    } else if (g == 1) {
                        zz[nt][e] = sigmoidf_(gi + gh);
                    } else {
                        float ng = tanhf(gi + rr[nt][e] * gh);
                        float hv = hs[r][c];
                        float v = (1.f - zz[nt][e]) * ng + zz[nt][e] * hv;
                        int node = n0 + r;
                        if (node < NNODES)
                            out[(size_t)NNODES * 64 + (size_t)node * 64 + c] = v;
                        nh[r][c] = __uint_as_float(f2tf(v));
                    }
                }
            }
        }
        __syncthreads();  // nh complete

        // output projection: source = nh @ Wout + bout
        float(*Wo)[WS_STRIDE] = (float(*)[WS_STRIDE])(wsm + 6 * 64 * WS_STRIDE);
        float C[4][4];
#pragma unroll
        for (int nt = 0; nt < 4; ++nt)
#pragma unroll
            for (int e = 0; e < 4; ++e) C[nt][e] = 0.f;
#pragma unroll
        for (int ks = 0; ks < 8; ++ks) {
            int kb = ks * 8;
            unsigned a0 = __float_as_uint(nh[row0][kb + kq]);
            unsigned a1 = __float_as_uint(nh[row0 + 8][kb + kq]);
            unsigned a2 = __float_as_uint(nh[row0][kb + kq + 4]);
            unsigned a3 = __float_as_uint(nh[row0 + 8][kb + kq + 4]);
#pragma unroll
            for (int nt = 0; nt < 4; ++nt) {
                int col = colh + nt * 8 + cn;
                unsigned b0 = __float_as_uint(Wo[kb + kq][col]);
                unsigned b1 = __float_as_uint(Wo[kb + kq + 4][col]);
                mma_tf32(C[nt], a0, a1, a2, a3, b0, b1);
            }
        }
#pragma unroll
        for (int nt = 0; nt < 4; ++nt) {
            int c0 = colh + nt * 8 + (lane & 3) * 2;
            float ba = bout[c0], bb = bout[c0 + 1];
            if (node0 < NNODES)
                *(float2*)&out[(size_t)node0 * 64 + c0] =
                    make_float2(C[nt][0] + ba, C[nt][1] + bb);
            if (node1 < NNODES)
                *(float2*)&out[(size_t)node1 * 64 + c0] =
                    make_float2(C[nt][2] + ba, C[nt][3] + bb);
        }
        __syncthreads();  // before overwriting ms/hs/nh next tile
    }
}

// ---------------- launch ---------------------------------------------------
extern "C" void kernel_launch(void* const* d_in, const int* in_sizes, int n_in,
                              void* d_out, int out_size) {
    const float* x    = (const float*)d_in[0];
    const float* hin  = (const float*)d_in[1];
    const int*   srcp = (const int*)d_in[2];
    const float* Wm   = (const float*)d_in[4];
    const float* bm   = (const float*)d_in[5];
    const float* Wg   = (const float*)d_in[6];
    const float* bg   = (const float*)d_in[7];
    const float* Wfc  = (const float*)d_in[8];
    const float* al   = (const float*)d_in[9];
    const float* ar   = (const float*)d_in[10];
    const float* Wmg  = (const float*)d_in[11];
    const float* bmg  = (const float*)d_in[12];
    const float* Wih  = (const float*)d_in[13];
    const float* Whh  = (const float*)d_in[14];
    const float* bih  = (const float*)d_in[15];
    const float* bhh  = (const float*)d_in[16];
    const float* Wo   = (const float*)d_in[17];
    const float* bo   = (const float*)d_in[18];
    float* out = (float*)d_out;

    cudaFuncSetAttribute(k1_node_linear, cudaFuncAttributeMaxDynamicSharedMemorySize, K1_SMEM);
    cudaFuncSetAttribute(k3_fused, cudaFuncAttributeMaxDynamicSharedMemorySize, K3_SMEM);

    k0_fold_attn<<<1, 128>>>(Wfc, al, ar);
    k0_fold_U<<<dim3(128, 2), 64>>>(Wfc, Wmg);
    k1_node_linear<<<GRID_P, 256, K1_SMEM>>>(x, Wm, bm, Wg, Wmg);
    k2_aggregate<<<(NNODES + 7) / 8, 256>>>(srcp, Wg, bg);
    k3_fused<<<GRID_P, 256, K3_SMEM>>>(bmg, hin, Wih, Whh, bih, bhh, Wo, bo, out);
}

// round 11
// speedup vs baseline: 1.2257x; 1.1879x over previous
#include <cuda_runtime.h>
#include <math.h>

#define NNODES 50000
#define DEGC 16
#define RECS 208    // record: y[128] z[64] el[2] er[2] xg2[2] xg1[2]
#define NT128 391   // 128-node tiles
#define GRID_P 148

// ---------------- scratch (device globals) ---------------------------------
__device__ float g_rec[NNODES * RECS];
__device__ float g_gy[NNODES * 64];
__device__ float g_xm[NNODES * 64];
__device__ float g_vlr[128 * 4];
__device__ float g_U[2 * 128 * 64];

__device__ __forceinline__ float sigmoidf_(float v) { return 1.f / (1.f + __expf(-v)); }

__device__ __forceinline__ unsigned f2tf(float v) {
    unsigned r;
    asm("cvt.rna.tf32.f32 %0, %1;" : "=r"(r) : "f"(v));
    return r;
}

__device__ __forceinline__ void mma_tf32(float c[4], unsigned a0, unsigned a1,
                                         unsigned a2, unsigned a3,
                                         unsigned b0, unsigned b1) {
    asm volatile(
        "mma.sync.aligned.m16n8k8.row.col.f32.tf32.tf32.f32 "
        "{%0,%1,%2,%3}, {%4,%5,%6,%7}, {%8,%9}, {%0,%1,%2,%3};"
        : "+f"(c[0]), "+f"(c[1]), "+f"(c[2]), "+f"(c[3])
        : "r"(a0), "r"(a1), "r"(a2), "r"(a3), "r"(b0), "r"(b1));
}

#define XS_STRIDE 140
#define WS_STRIDE 72
#define MS_STRIDE 76
// k1 smem floats: ws 4*128*72=36864 | vs 1024 | xs 128*140=17920 -> 55808 fl = 223232 B
#define K1_SMEM (55808 * 4)
// k3 smem floats: ws 7*64*72=32256 | ms 128*76=9728 | hs 128*76=9728 -> 51712 fl = 206848 B
#define K3_SMEM (51712 * 4)

// ---------------- K0a: fold attn vectors -----------------------------------
__global__ void k0_fold_attn(const float* __restrict__ Wfc,
                             const float* __restrict__ al,
                             const float* __restrict__ ar) {
    int k = threadIdx.x;  // 128
#pragma unroll
    for (int h = 0; h < 2; ++h) {
        float sl = 0.f, sr = 0.f;
#pragma unroll 8
        for (int q = 0; q < 64; ++q) {
            float w = Wfc[k * 128 + h * 64 + q];
            sl += w * al[h * 64 + q];
            sr += w * ar[h * 64 + q];
        }
        g_vlr[k * 4 + h] = sl;
        g_vlr[k * 4 + 2 + h] = sr;
    }
}

// ---------------- K0b: U_h = Wfc_h @ Wmerge2_h -----------------------------
__global__ void k0_fold_U(const float* __restrict__ Wfc,
                          const float* __restrict__ Wmerge) {
    int k = blockIdx.x, h = blockIdx.y, c = threadIdx.x;
    float s = 0.f;
#pragma unroll 8
    for (int q = 0; q < 64; ++q)
        s += Wfc[k * 128 + h * 64 + q] * Wmerge[(128 + h * 64 + q) * 64 + c];
    g_U[(h * 128 + k) * 64 + c] = s;
}

// ---------------- K1 persistent, 512 threads, 128-node tiles ---------------
__global__ __launch_bounds__(512) void k1_node_linear(
    const float* __restrict__ x, const float* __restrict__ Wm,
    const float* __restrict__ bm, const float* __restrict__ Wg,
    const float* __restrict__ Wmerge) {
    extern __shared__ float sm[];
    float* wsm = sm;                                   // [4][128][72]
    float* vs = sm + 4 * 128 * WS_STRIDE;              // [128][8]
    float(*xs)[XS_STRIDE] = (float(*)[XS_STRIDE])(sm + 4 * 128 * WS_STRIDE + 1024);
    const int tid = threadIdx.x, lane = tid & 31, wid = tid >> 5;
    const int row0 = (wid >> 1) * 16 + (lane >> 2);    // 8 rowgroups x 16 = 128
    const int colh = (wid & 1) * 32;
    const int kq = lane & 3;
    const int cn = lane >> 2;

    // ---- load all weights once ----
    for (int idx = tid; idx < 4 * 128 * 64; idx += 512) {
        int p = idx >> 13, rem = idx & 8191, k = rem >> 6, c = rem & 63;
        float w;
        if (p == 0) w = Wm[k * 64 + c];
        else if (p == 3) w = Wmerge[k * 64 + c];
        else w = g_U[((p - 1) * 128 + k) * 64 + c];
        wsm[p * 128 * WS_STRIDE + k * WS_STRIDE + c] = __uint_as_float(f2tf(w));
    }
    for (int idx = tid; idx < 1024; idx += 512) {
        int k = idx >> 3, c = idx & 7;
        float v;
        if (c < 4) v = g_vlr[k * 4 + c];
        else if (c < 6) v = Wg[(128 + k) * 2 + (c - 4)];
        else v = Wg[k * 2 + (c - 6)];
        vs[idx] = v;
    }

    // ---- first tile load ----
    int t = blockIdx.x;
    {
        int n0 = t * 128;
#pragma unroll
        for (int i = 0; i < 32; ++i) {
            int idx = tid + i * 512, nn = idx >> 7, k = idx & 127;
            int node = n0 + nn;
            xs[nn][k] = __uint_as_float(f2tf((node < NNODES) ? x[node * 128 + k] : 0.f));
        }
    }
    __syncthreads();

    for (;;) {
        const int tn = t + GRID_P;
        const bool hasnext = tn < NT128;
        float pf[32];
        if (hasnext) {
            int n0n = tn * 128;
#pragma unroll
            for (int i = 0; i < 32; ++i) {
                int idx = tid + i * 512, nn = idx >> 7, k = idx & 127;
                int node = n0n + nn;
                pf[i] = (node < NNODES) ? x[node * 128 + k] : 0.f;
            }
        }

        const int n0 = t * 128;
        const int node0 = n0 + row0, node1 = node0 + 8;

        // 4 GEMM passes, weights resident, no syncs between
#pragma unroll
        for (int pass = 0; pass < 4; ++pass) {
            float(*W)[WS_STRIDE] = (float(*)[WS_STRIDE])(wsm + pass * 128 * WS_STRIDE);
            float C[4][4];
#pragma unroll
            for (int nt = 0; nt < 4; ++nt)
#pragma unroll
                for (int e = 0; e < 4; ++e) C[nt][e] = 0.f;
#pragma unroll
            for (int ks = 0; ks < 16; ++ks) {
                int kb = ks * 8;
                unsigned a0 = __float_as_uint(xs[row0][kb + kq]);
                unsigned a1 = __float_as_uint(xs[row0 + 8][kb + kq]);
                unsigned a2 = __float_as_uint(xs[row0][kb + kq + 4]);
                unsigned a3 = __float_as_uint(xs[row0 + 8][kb + kq + 4]);
#pragma unroll
                for (int nt = 0; nt < 4; ++nt) {
                    int col = colh + nt * 8 + cn;
                    unsigned b0 = __float_as_uint(W[kb + kq][col]);
                    unsigned b1 = __float_as_uint(W[kb + kq + 4][col]);
                    mma_tf32(C[nt], a0, a1, a2, a3, b0, b1);
                }
            }
            if (pass == 3) {
#pragma unroll
                for (int nt = 0; nt < 4; ++nt) {
                    int c0 = colh + nt * 8 + (lane & 3) * 2;
                    if (node0 < NNODES)
                        *(float2*)&g_xm[(size_t)node0 * 64 + c0] = make_float2(C[nt][0], C[nt][1]);
                    if (node1 < NNODES)
                        *(float2*)&g_xm[(size_t)node1 * 64 + c0] = make_float2(C[nt][2], C[nt][3]);
                }
            } else {
                int cbase = (pass == 0) ? 128 : (pass - 1) * 64;
#pragma unroll
                for (int nt = 0; nt < 4; ++nt) {
                    int c0 = colh + nt * 8 + (lane & 3) * 2;
                    float ba = 0.f, bb = 0.f;
                    if (pass == 0) { ba = bm[c0]; bb = bm[c0 + 1]; }
                    if (node0 < NNODES)
                        *(float2*)&g_rec[(size_t)node0 * RECS + cbase + c0] =
                            make_float2(C[nt][0] + ba, C[nt][1] + bb);
                    if (node1 < NNODES)
                        *(float2*)&g_rec[(size_t)node1 * RECS + cbase + c0] =
                            make_float2(C[nt][2] + ba, C[nt][3] + bb);
                }
            }
        }

        // scalar tail: 128 nodes x 8 = 1024 items
#pragma unroll
        for (int w = 0; w < 2; ++w) {
            int it = tid + w * 512;
            int nn = it >> 3, c = it & 7;
            float s = 0.f;
#pragma unroll 16
            for (int k = 0; k < 128; ++k) s += xs[nn][k] * vs[k * 8 + c];
            int node = n0 + nn;
            if (node < NNODES) g_rec[(size_t)node * RECS + 192 + c] = s;
        }

        __syncthreads();  // all xs reads done
        if (!hasnext) break;
#pragma unroll
        for (int i = 0; i < 32; ++i) {
            int idx = tid + i * 512, nn = idx >> 7, k = idx & 127;
            xs[nn][k] = __uint_as_float(f2tf(pf[i]));
        }
        t = tn;
        __syncthreads();
    }
}

// ---------------- K2: one warp per node, zero barriers ---------------------
__global__ __launch_bounds__(256) void k2_aggregate(
    const int* __restrict__ src, const float* __restrict__ Wg,
    const float* __restrict__ bg) {
    const unsigned FULL = 0xffffffffu;
    const int n = blockIdx.x * 8 + ((threadIdx.x) >> 5);
    if (n >= NNODES) return;
    const int lane = threadIdx.x & 31;
    const int j16 = lane & 15, h = lane >> 4;

    int srcj = src[n * DEGC + j16];

    float el = g_rec[(size_t)srcj * RECS + 192 + h];
    float er = g_rec[(size_t)n * RECS + 194 + h];
    float e = el + er;
    e = (e > 0.f) ? e : 0.2f * e;
    float m = e;
#pragma unroll
    for (int o = 8; o > 0; o >>= 1) m = fmaxf(m, __shfl_xor_sync(FULL, m, o));
    float ee = __expf(e - m);
    float s = ee;
#pragma unroll
    for (int o = 8; o > 0; o >>= 1) s += __shfl_xor_sync(FULL, s, o);
    float alpha = ee / fmaxf(s, 1e-12f);

    float xg2 = g_rec[(size_t)srcj * RECS + 196 + h];
#pragma unroll
    for (int o = 8; o > 0; o >>= 1) xg2 += __shfl_xor_sync(FULL, xg2, o);

    float mz0 = -3.4e38f, mz1 = -3.4e38f;
#pragma unroll
    for (int j = 0; j < 16; ++j) {
        int sj = __shfl_sync(FULL, srcj, j);
        float2 z2 = *(const float2*)&g_rec[(size_t)sj * RECS + 128 + 2 * lane];
        mz0 = fmaxf(mz0, z2.x);
        mz1 = fmaxf(mz1, z2.y);
    }
    float p0 = mz0 * Wg[(256 + 2 * lane) * 2 + 0] + mz1 * Wg[(256 + 2 * lane + 1) * 2 + 0];
    float p1 = mz0 * Wg[(256 + 2 * lane) * 2 + 1] + mz1 * Wg[(256 + 2 * lane + 1) * 2 + 1];
#pragma unroll
    for (int o = 16; o > 0; o >>= 1) {
        p0 += __shfl_xor_sync(FULL, p0, o);
        p1 += __shfl_xor_sync(FULL, p1, o);
    }
    float g3 = (h == 0) ? p0 : p1;
    float xg1 = g_rec[(size_t)n * RECS + 198 + h];
    float gate = sigmoidf_(xg1 + 0.0625f * xg2 + g3 + bg[h]);

    float4 acc = make_float4(0.f, 0.f, 0.f, 0.f);
#pragma unroll
    for (int j = 0; j < 16; ++j) {
        int sj = __shfl_sync(FULL, srcj, j);
        float a = __shfl_sync(FULL, alpha, (lane & 16) | j);
        float4 y4 = *(const float4*)&g_rec[(size_t)sj * RECS + 4 * lane];
        acc.x += a * y4.x; acc.y += a * y4.y; acc.z += a * y4.z; acc.w += a * y4.w;
    }

    float got = __shfl_xor_sync(FULL, gate, 16);
    float ox = __shfl_xor_sync(FULL, acc.x, 16);
    float oy = __shfl_xor_sync(FULL, acc.y, 16);
    float oz = __shfl_xor_sync(FULL, acc.z, 16);
    float ow = __shfl_xor_sync(FULL, acc.w, 16);
    if (lane < 16) {
        float4 gy;
        gy.x = gate * acc.x + got * ox;
        gy.y = gate * acc.y + got * oy;
        gy.z = gate * acc.z + got * oz;
        gy.w = gate * acc.w + got * ow;
        *(float4*)&g_gy[(size_t)n * 64 + 4 * lane] = gy;
    }
}

// ---------------- K3 persistent, 512 threads, 128-node tiles ---------------
__global__ __launch_bounds__(512) void k3_fused(
    const float* __restrict__ bmerge,
    const float* __restrict__ hin, const float* __restrict__ W_ih,
    const float* __restrict__ W_hh, const float* __restrict__ b_ih,
    const float* __restrict__ b_hh, const float* __restrict__ Wout,
    const float* __restrict__ bout, float* __restrict__ out) {
    extern __shared__ float sm[];
    float* wsm = sm;                                    // [7][64][72]
    float(*ms)[MS_STRIDE] = (float(*)[MS_STRIDE])(sm + 7 * 64 * WS_STRIDE);
    float(*hs)[MS_STRIDE] = (float(*)[MS_STRIDE])(sm + 7 * 64 * WS_STRIDE + 128 * MS_STRIDE);
    float(*nh)[MS_STRIDE] = ms;   // alias: ms dead after g=2 mma (fenced by barrier)
    const int tid = threadIdx.x, lane = tid & 31, wid = tid >> 5;
    const int row0 = (wid >> 1) * 16 + (lane >> 2);    // 128 rows
    const int colh = (wid & 1) * 32;
    const int kq = lane & 3;
    const int cn = lane >> 2;

    // ---- load all weights once: 0..2 W_ih, 3..5 W_hh, 6 Wout ----
    for (int idx = tid; idx < 7 * 64 * 64; idx += 512) {
        int p = idx >> 12, rem = idx & 4095, k = rem >> 6, c = rem & 63;
        float w;
        if (p < 3) w = W_ih[(p * 64 + c) * 64 + k];
        else if (p < 6) w = W_hh[((p - 3) * 64 + c) * 64 + k];
        else w = Wout[k * 64 + c];
        wsm[p * 64 * WS_STRIDE + k * WS_STRIDE + c] = __uint_as_float(f2tf(w));
    }
    __syncthreads();

    for (int t = blockIdx.x; t < NT128; t += GRID_P) {
        const int n0 = t * 128;
        const int node0 = n0 + row0, node1 = node0 + 8;

        // load ms (= xm + gy + bmerge) and h tile: 128x64 each
        for (int idx = tid; idx < 128 * 64; idx += 512) {
            int nn = idx >> 6, k = idx & 63;
            int node = n0 + nn;
            float mv = 0.f, hv = 0.f;
            if (node < NNODES) {
                mv = g_xm[(size_t)node * 64 + k] + g_gy[(size_t)node * 64 + k] + bmerge[k];
                hv = hin[node * 64 + k];
            }
            ms[nn][k] = __uint_as_float(f2tf(mv));
            hs[nn][k] = hv;
        }
        __syncthreads();

        float rr[4][4], zz[4][4];
#pragma unroll
        for (int g = 0; g < 3; ++g) {
            float(*Wi)[WS_STRIDE] = (float(*)[WS_STRIDE])(wsm + g * 64 * WS_STRIDE);
            float(*Wh)[WS_STRIDE] = (float(*)[WS_STRIDE])(wsm + (3 + g) * 64 * WS_STRIDE);
            float ai[4][4], ah[4][4];
#pragma unroll
            for (int nt = 0; nt < 4; ++nt)
#pragma unroll
                for (int e = 0; e < 4; ++e) { ai[nt][e] = 0.f; ah[nt][e] = 0.f; }
#pragma unroll
            for (int ks = 0; ks < 8; ++ks) {
                int kb = ks * 8;
                unsigned a0 = __float_as_uint(ms[row0][kb + kq]);
                unsigned a1 = __float_as_uint(ms[row0 + 8][kb + kq]);
                unsigned a2 = __float_as_uint(ms[row0][kb + kq + 4]);
                unsigned a3 = __float_as_uint(ms[row0 + 8][kb + kq + 4]);
                unsigned h0 = __float_as_uint(hs[row0][kb + kq]);
                unsigned h1 = __float_as_uint(hs[row0 + 8][kb + kq]);
                unsigned h2 = __float_as_uint(hs[row0][kb + kq + 4]);
                unsigned h3 = __float_as_uint(hs[row0 + 8][kb + kq + 4]);
#pragma unroll
                for (int nt = 0; nt < 4; ++nt) {
                    int col = colh + nt * 8 + cn;
                    unsigned bi0 = __float_as_uint(Wi[kb + kq][col]);
                    unsigned bi1 = __float_as_uint(Wi[kb + kq + 4][col]);
                    unsigned bh0 = __float_as_uint(Wh[kb + kq][col]);
                    unsigned bh1 = __float_as_uint(Wh[kb + kq + 4][col]);
                    mma_tf32(ai[nt], a0, a1, a2, a3, bi0, bi1);
                    mma_tf32(ah[nt], h0, h1, h2, h3, bh0, bh1);
                }
            }

            if (g == 2) __syncthreads();  // all ms reads done before nh overwrite

#pragma unroll
            for (int nt = 0; nt < 4; ++nt) {
#pragma unroll
                for (int e = 0; e < 4; ++e) {
                    int c = colh + nt * 8 + (lane & 3) * 2 + (e & 1);
                    int r = row0 + (e >> 1) * 8;
                    float gi = ai[nt][e] + b_ih[g * 64 + c];
                    float gh = ah[nt][e] + b_hh[g * 64 + c];
                    if (g == 0) {
                        rr[nt][e] = sigmoidf_(gi + gh);
                    } else if (g == 1) {
                        zz[nt][e] = sigmoidf_(gi + gh);
                    } else {
                        float ng = tanhf(gi + rr[nt][e] * gh);
                        float hv = hs[r][c];
                        float v = (1.f - zz[nt][e]) * ng + zz[nt][e] * hv;
                        int node = n0 + r;
                        if (node < NNODES)
                            out[(size_t)NNODES * 64 + (size_t)node * 64 + c] = v;
                        nh[r][c] = __uint_as_float(f2tf(v));
                    }
                }
            }
        }
        __syncthreads();  // nh complete

        // output projection: source = nh @ Wout + bout
        float(*Wo)[WS_STRIDE] = (float(*)[WS_STRIDE])(wsm + 6 * 64 * WS_STRIDE);
        float C[4][4];
#pragma unroll
        for (int nt = 0; nt < 4; ++nt)
#pragma unroll
            for (int e = 0; e < 4; ++e) C[nt][e] = 0.f;
#pragma unroll
        for (int ks = 0; ks < 8; ++ks) {
            int kb = ks * 8;
            unsigned a0 = __float_as_uint(nh[row0][kb + kq]);
            unsigned a1 = __float_as_uint(nh[row0 + 8][kb + kq]);
            unsigned a2 = __float_as_uint(nh[row0][kb + kq + 4]);
            unsigned a3 = __float_as_uint(nh[row0 + 8][kb + kq + 4]);
#pragma unroll
            for (int nt = 0; nt < 4; ++nt) {
                int col = colh + nt * 8 + cn;
                unsigned b0 = __float_as_uint(Wo[kb + kq][col]);
                unsigned b1 = __float_as_uint(Wo[kb + kq + 4][col]);
                mma_tf32(C[nt], a0, a1, a2, a3, b0, b1);
            }
        }
#pragma unroll
        for (int nt = 0; nt < 4; ++nt) {
            int c0 = colh + nt * 8 + (lane & 3) * 2;
            float ba = bout[c0], bb = bout[c0 + 1];
            if (node0 < NNODES)
                *(float2*)&out[(size_t)node0 * 64 + c0] =
                    make_float2(C[nt][0] + ba, C[nt][1] + bb);
            if (node1 < NNODES)
                *(float2*)&out[(size_t)node1 * 64 + c0] =
                    make_float2(C[nt][2] + ba, C[nt][3] + bb);
        }
        __syncthreads();  // before overwriting ms/hs next tile
    }
}

// ---------------- launch ---------------------------------------------------
extern "C" void kernel_launch(void* const* d_in, const int* in_sizes, int n_in,
                              void* d_out, int out_size) {
    const float* x    = (const float*)d_in[0];
    const float* hin  = (const float*)d_in[1];
    const int*   srcp = (const int*)d_in[2];
    const float* Wm   = (const float*)d_in[4];
    const float* bm   = (const float*)d_in[5];
    const float* Wg   = (const float*)d_in[6];
    const float* bg   = (const float*)d_in[7];
    const float* Wfc  = (const float*)d_in[8];
    const float* al   = (const float*)d_in[9];
    const float* ar   = (const float*)d_in[10];
    const float* Wmg  = (const float*)d_in[11];
    const float* bmg  = (const float*)d_in[12];
    const float* Wih  = (const float*)d_in[13];
    const float* Whh  = (const float*)d_in[14];
    const float* bih  = (const float*)d_in[15];
    const float* bhh  = (const float*)d_in[16];
    const float* Wo   = (const float*)d_in[17];
    const float* bo   = (const float*)d_in[18];
    float* out = (float*)d_out;

    cudaFuncSetAttribute(k1_node_linear, cudaFuncAttributeMaxDynamicSharedMemorySize, K1_SMEM);
    cudaFuncSetAttribute(k3_fused, cudaFuncAttributeMaxDynamicSharedMemorySize, K3_SMEM);

    k0_fold_attn<<<1, 128>>>(Wfc, al, ar);
    k0_fold_U<<<dim3(128, 2), 64>>>(Wfc, Wmg);
    k1_node_linear<<<GRID_P, 512, K1_SMEM>>>(x, Wm, bm, Wg, Wmg);
    k2_aggregate<<<(NNODES + 7) / 8, 256>>>(srcp, Wg, bg);
    k3_fused<<<GRID_P, 512, K3_SMEM>>>(bmg, hin, Wih, Whh, bih, bhh, Wo, bo, out);
}

// round 13
// speedup vs baseline: 1.2400x; 1.0117x over previous
#include <cuda_runtime.h>
#include <math.h>

#define NNODES 50000
#define DEGC 16
#define RECS 208    // record: y[128] z[64] el[2] er[2] xg2[2] xg1[2]
#define NT128 391   // 128-node tiles
#define GRID_P 148

// ---------------- scratch (device globals) ---------------------------------
__device__ float g_rec[NNODES * RECS];
__device__ float g_gy[NNODES * 64];
__device__ float g_xm[NNODES * 64];
__device__ float g_vlr[128 * 4];
__device__ float g_U[2 * 128 * 64];

__device__ __forceinline__ float sigmoidf_(float v) { return 1.f / (1.f + __expf(-v)); }

__device__ __forceinline__ unsigned f2tf(float v) {
    unsigned r;
    asm("cvt.rna.tf32.f32 %0, %1;" : "=r"(r) : "f"(v));
    return r;
}

__device__ __forceinline__ void mma_tf32(float c[4], unsigned a0, unsigned a1,
                                         unsigned a2, unsigned a3,
                                         unsigned b0, unsigned b1) {
    asm volatile(
        "mma.sync.aligned.m16n8k8.row.col.f32.tf32.tf32.f32 "
        "{%0,%1,%2,%3}, {%4,%5,%6,%7}, {%8,%9}, {%0,%1,%2,%3};"
        : "+f"(c[0]), "+f"(c[1]), "+f"(c[2]), "+f"(c[3])
        : "r"(a0), "r"(a1), "r"(a2), "r"(a3), "r"(b0), "r"(b1));
}

// k1 smem (floats): wbA 16384 | wbB 16384 | wsc 1024 | xa 16384 -> 50176 = 200704 B
#define K1_WBA 0
#define K1_WBB 16384
#define K1_WSC 32768
#define K1_XA  33792
#define K1_SMEM (50176 * 4)
// k3 smem (floats): wbA 14336 | wbB 14336 | ma 8192 | ha 8192 -> 45056 = 180224 B
#define K3_WBA 0
#define K3_WBB 14336
#define K3_MA  28672
#define K3_HA  36864
#define K3_SMEM (45056 * 4)

// ---------------- K0a: fold attn vectors -----------------------------------
__global__ void k0_fold_attn(const float* __restrict__ Wfc,
                             const float* __restrict__ al,
                             const float* __restrict__ ar) {
    int k = threadIdx.x;  // 128
#pragma unroll
    for (int h = 0; h < 2; ++h) {
        float sl = 0.f, sr = 0.f;
#pragma unroll 8
        for (int q = 0; q < 64; ++q) {
            float w = Wfc[k * 128 + h * 64 + q];
            sl += w * al[h * 64 + q];
            sr += w * ar[h * 64 + q];
        }
        g_vlr[k * 4 + h] = sl;
        g_vlr[k * 4 + 2 + h] = sr;
    }
}

// ---------------- K0b: U_h = Wfc_h @ Wmerge2_h -----------------------------
__global__ void k0_fold_U(const float* __restrict__ Wfc,
                          const float* __restrict__ Wmerge) {
    int k = blockIdx.x, h = blockIdx.y, c = threadIdx.x;
    float s = 0.f;
#pragma unroll 8
    for (int q = 0; q < 64; ++q)
        s += Wfc[k * 128 + h * 64 + q] * Wmerge[(128 + h * 64 + q) * 64 + c];
    g_U[(h * 128 + k) * 64 + c] = s;
}

// ---------------- K1 persistent, fragment-packed smem ----------------------
__global__ __launch_bounds__(512) void k1_node_linear(
    const float* __restrict__ x, const float* __restrict__ Wm,
    const float* __restrict__ bm, const float* __restrict__ Wg,
    const float* __restrict__ Wmerge) {
    extern __shared__ float sm[];
    float* wbA = sm + K1_WBA;
    float* wbB = sm + K1_WBB;
    float* wsc = sm + K1_WSC;
    float* xa  = sm + K1_XA;
    const int tid = threadIdx.x, lane = tid & 31, wid = tid >> 5;
    const int rg = wid >> 1;           // rowgroup 0..7
    const int ch = wid & 1;            // column half
    const int row0 = rg * 16 + (lane >> 2);
    const int colh = ch * 32;

    // ---- pack weights (once): value w(p,k,c) -> fragment layout ----
    for (int idx = tid; idx < 4 * 128 * 64; idx += 512) {
        int p = idx >> 13, rem = idx & 8191, k = rem >> 6, c = rem & 63;
        float w;
        if (p == 0) w = Wm[k * 64 + c];
        else if (p == 3) w = Wmerge[k * 64 + c];
        else w = g_U[((p - 1) * 128 + k) * 64 + c];
        int l = (c & 7) * 4 + (k & 3);
        int pi = ((((p * 2 + (c >> 5)) * 16 + (k >> 3)) * 32 + l) << 2)
                 + ((c >> 3) & 1) * 2 + ((k >> 2) & 1);
        if ((c >> 4) & 1) wbB[pi] = __uint_as_float(f2tf(w));
        else              wbA[pi] = __uint_as_float(f2tf(w));
    }
    // scalar tile weights: 8 cols per k: el0,el1,er0,er1,xg2_0,xg2_1,xg1_0,xg1_1
    for (int idx = tid; idx < 128 * 8; idx += 512) {
        int k = idx >> 3, c = idx & 7;
        float v;
        if (c < 4) v = g_vlr[k * 4 + c];
        else if (c < 6) v = Wg[(128 + k) * 2 + (c - 4)];
        else v = Wg[k * 2 + (c - 6)];
        int l = c * 4 + (k & 3);
        int pi = (((k >> 3) * 32 + l) << 1) + ((k >> 2) & 1);
        wsc[pi] = __uint_as_float(f2tf(v));
    }

    for (int t = blockIdx.x; t < NT128; t += GRID_P) {
        const int n0 = t * 128;
        __syncthreads();  // prior readers done / weights packed
        for (int idx = tid; idx < 128 * 128; idx += 512) {
            int nn = idx >> 7, k = idx & 127;
            int node = n0 + nn;
            float v = (node < NNODES) ? x[node * 128 + k] : 0.f;
            int l = ((nn & 7) << 2) | (k & 3);
            int j = ((nn >> 3) & 1) | (((k >> 2) & 1) << 1);
            int pi = (((((nn >> 4) << 4) + (k >> 3)) * 32 + l) << 2) | j;
            xa[pi] = __uint_as_float(f2tf(v));
        }
        __syncthreads();

        float C[4][4][4];   // [pass][nt][e]
        float Cs[4];
#pragma unroll
        for (int p = 0; p < 4; ++p)
#pragma unroll
            for (int nt = 0; nt < 4; ++nt)
#pragma unroll
                for (int e = 0; e < 4; ++e) C[p][nt][e] = 0.f;
#pragma unroll
        for (int e = 0; e < 4; ++e) Cs[e] = 0.f;

#pragma unroll
        for (int ks = 0; ks < 16; ++ks) {
            float4 av = *(const float4*)&xa[(((rg << 4) + ks) * 32 + lane) << 2];
            unsigned a0 = __float_as_uint(av.x), a1 = __float_as_uint(av.y),
                     a2 = __float_as_uint(av.z), a3 = __float_as_uint(av.w);
#pragma unroll
            for (int p = 0; p < 4; ++p) {
                int bi = ((((p * 2 + ch) << 4) + ks) * 32 + lane) << 2;
                float4 b01 = *(const float4*)&wbA[bi];
                float4 b23 = *(const float4*)&wbB[bi];
                mma_tf32(C[p][0], a0, a1, a2, a3,
                         __float_as_uint(b01.x), __float_as_uint(b01.y));
                mma_tf32(C[p][1], a0, a1, a2, a3,
                         __float_as_uint(b01.z), __float_as_uint(b01.w));
                mma_tf32(C[p][2], a0, a1, a2, a3,
                         __float_as_uint(b23.x), __float_as_uint(b23.y));
                mma_tf32(C[p][3], a0, a1, a2, a3,
                         __float_as_uint(b23.z), __float_as_uint(b23.w));
            }
            if (ch == 0) {
                float2 sb = *(const float2*)&wsc[((ks * 32 + lane) << 1)];
                mma_tf32(Cs, a0, a1, a2, a3,
                         __float_as_uint(sb.x), __float_as_uint(sb.y));
            }
        }

        const int node0 = n0 + row0, node1 = node0 + 8;
#pragma unroll
        for (int p = 0; p < 4; ++p) {
            if (p == 3) {
#pragma unroll
                for (int nt = 0; nt < 4; ++nt) {
                    int c0 = colh + nt * 8 + (lane & 3) * 2;
                    if (node0 < NNODES)
                        *(float2*)&g_xm[(size_t)node0 * 64 + c0] =
                            make_float2(C[3][nt][0], C[3][nt][1]);
                    if (node1 < NNODES)
                        *(float2*)&g_xm[(size_t)node1 * 64 + c0] =
                            make_float2(C[3][nt][2], C[3][nt][3]);
                }
            } else {
                int cbase = (p == 0) ? 128 : (p - 1) * 64;
#pragma unroll
                for (int nt = 0; nt < 4; ++nt) {
                    int c0 = colh + nt * 8 + (lane & 3) * 2;
                    float ba = 0.f, bb = 0.f;
                    if (p == 0) { ba = bm[c0]; bb = bm[c0 + 1]; }
                    if (node0 < NNODES)
                        *(float2*)&g_rec[(size_t)node0 * RECS + cbase + c0] =
                            make_float2(C[p][nt][0] + ba, C[p][nt][1] + bb);
                    if (node1 < NNODES)
                        *(float2*)&g_rec[(size_t)node1 * RECS + cbase + c0] =
                            make_float2(C[p][nt][2] + ba, C[p][nt][3] + bb);
                }
            }
        }
        if (ch == 0) {
            int c0 = (lane & 3) * 2;
            if (node0 < NNODES)
                *(float2*)&g_rec[(size_t)node0 * RECS + 192 + c0] =
                    make_float2(Cs[0], Cs[1]);
            if (node1 < NNODES)
                *(float2*)&g_rec[(size_t)node1 * RECS + 192 + c0] =
                    make_float2(Cs[2], Cs[3]);
        }
    }
}

// ---------------- K2: one warp per node, zero barriers ---------------------
__global__ __launch_bounds__(256) void k2_aggregate(
    const int* __restrict__ src, const float* __restrict__ Wg,
    const float* __restrict__ bg) {
    const unsigned FULL = 0xffffffffu;
    const int n = blockIdx.x * 8 + ((threadIdx.x) >> 5);
    if (n >= NNODES) return;
    const int lane = threadIdx.x & 31;
    const int j16 = lane & 15, h = lane >> 4;

    int srcj = src[n * DEGC + j16];

    float el = g_rec[(size_t)srcj * RECS + 192 + h];
    float er = g_rec[(size_t)n * RECS + 194 + h];
    float e = el + er;
    e = (e > 0.f) ? e : 0.2f * e;
    float m = e;
#pragma unroll
    for (int o = 8; o > 0; o >>= 1) m = fmaxf(m, __shfl_xor_sync(FULL, m, o));
    float ee = __expf(e - m);
    float s = ee;
#pragma unroll
    for (int o = 8; o > 0; o >>= 1) s += __shfl_xor_sync(FULL, s, o);
    float alpha = ee / fmaxf(s, 1e-12f);

    float xg2 = g_rec[(size_t)srcj * RECS + 196 + h];
#pragma unroll
    for (int o = 8; o > 0; o >>= 1) xg2 += __shfl_xor_sync(FULL, xg2, o);

    float mz0 = -3.4e38f, mz1 = -3.4e38f;
#pragma unroll
    for (int j = 0; j < 16; ++j) {
        int sj = __shfl_sync(FULL, srcj, j);
        float2 z2 = *(const float2*)&g_rec[(size_t)sj * RECS + 128 + 2 * lane];
        mz0 = fmaxf(mz0, z2.x);
        mz1 = fmaxf(mz1, z2.y);
    }
    float p0 = mz0 * Wg[(256 + 2 * lane) * 2 + 0] + mz1 * Wg[(256 + 2 * lane + 1) * 2 + 0];
    float p1 = mz0 * Wg[(256 + 2 * lane) * 2 + 1] + mz1 * Wg[(256 + 2 * lane + 1) * 2 + 1];
#pragma unroll
    for (int o = 16; o > 0; o >>= 1) {
        p0 += __shfl_xor_sync(FULL, p0, o);
        p1 += __shfl_xor_sync(FULL, p1, o);
    }
    float g3 = (h == 0) ? p0 : p1;
    float xg1 = g_rec[(size_t)n * RECS + 198 + h];
    float gate = sigmoidf_(xg1 + 0.0625f * xg2 + g3 + bg[h]);

    float4 acc = make_float4(0.f, 0.f, 0.f, 0.f);
#pragma unroll
    for (int j = 0; j < 16; ++j) {
        int sj = __shfl_sync(FULL, srcj, j);
        float a = __shfl_sync(FULL, alpha, (lane & 16) | j);
        float4 y4 = *(const float4*)&g_rec[(size_t)sj * RECS + 4 * lane];
        acc.x += a * y4.x; acc.y += a * y4.y; acc.z += a * y4.z; acc.w += a * y4.w;
    }

    float got = __shfl_xor_sync(FULL, gate, 16);
    float ox = __shfl_xor_sync(FULL, acc.x, 16);
    float oy = __shfl_xor_sync(FULL, acc.y, 16);
    float oz = __shfl_xor_sync(FULL, acc.z, 16);
    float ow = __shfl_xor_sync(FULL, acc.w, 16);
    if (lane < 16) {
        float4 gy;
        gy.x = gate * acc.x + got * ox;
        gy.y = gate * acc.y + got * oy;
        gy.z = gate * acc.z + got * oz;
        gy.w = gate * acc.w + got * ow;
        *(float4*)&g_gy[(size_t)n * 64 + 4 * lane] = gy;
    }
}

// ---------------- K3 persistent, fragment-packed smem ----------------------
__global__ __launch_bounds__(512) void k3_fused(
    const float* __restrict__ bmerge,
    const float* __restrict__ hin, const float* __restrict__ W_ih,
    const float* __restrict__ W_hh, const float* __restrict__ b_ih,
    const float* __restrict__ b_hh, const float* __restrict__ Wout,
    const float* __restrict__ bout, float* __restrict__ out) {
    extern __shared__ float sm[];
    float* wbA = sm + K3_WBA;
    float* wbB = sm + K3_WBB;
    float* ma  = sm + K3_MA;   // meso packed; aliased by nh after g==2 (fenced)
    float* ha  = sm + K3_HA;   // hidden packed (fp32)
    const int tid = threadIdx.x, lane = tid & 31, wid = tid >> 5;
    const int rg = wid >> 1;
    const int ch = wid & 1;
    const int row0 = rg * 16 + (lane >> 2);
    const int colh = ch * 32;

    // ---- pack 7 weight matrices: 0..2 W_ih, 3..5 W_hh, 6 Wout ----
    for (int idx = tid; idx < 7 * 64 * 64; idx += 512) {
        int mm = idx >> 12, rem = idx & 4095, k = rem >> 6, c = rem & 63;
        float w;
        if (mm < 3) w = W_ih[(mm * 64 + c) * 64 + k];
        else if (mm < 6) w = W_hh[((mm - 3) * 64 + c) * 64 + k];
        else w = Wout[k * 64 + c];
        int l = (c & 7) * 4 + (k & 3);
        int pi = ((((mm * 2 + (c >> 5)) << 3) + (k >> 3)) * 32 + l) * 4
                 + ((c >> 3) & 1) * 2 + ((k >> 2) & 1);
        if ((c >> 4) & 1) wbB[pi] = __uint_as_float(f2tf(w));
        else              wbA[pi] = __uint_as_float(f2tf(w));
    }

    for (int t = blockIdx.x; t < NT128; t += GRID_P) {
        const int n0 = t * 128;
        const int node0 = n0 + row0, node1 = node0 + 8;
        __syncthreads();  // prior tile readers done / weights packed

        // fill ms (= xm + gy + bmerge, tf32) and h tile, fragment-packed
        for (int idx = tid; idx < 128 * 64; idx += 512) {
            int nn = idx >> 6, k = idx & 63;
            int node = n0 + nn;
            float mv = 0.f, hv = 0.f;
            if (node < NNODES) {
                mv = g_xm[(size_t)node * 64 + k] + g_gy[(size_t)node * 64 + k] + bmerge[k];
                hv = hin[node * 64 + k];
            }
            int l = ((nn & 7) << 2) | (k & 3);
            int j = ((nn >> 3) & 1) | (((k >> 2) & 1) << 1);
            int pi = (((((nn >> 4) << 3) + (k >> 3)) * 32 + l) << 2) | j;
            ma[pi] = __uint_as_float(f2tf(mv));
            ha[pi] = hv;
        }
        __syncthreads();

        float rr[4][4], zz[4][4];
#pragma unroll
        for (int g = 0; g < 3; ++g) {
            float ai[4][4], ah[4][4];
#pragma unroll
            for (int nt = 0; nt < 4; ++nt)
#pragma unroll
                for (int e = 0; e < 4; ++e) { ai[nt][e] = 0.f; ah[nt][e] = 0.f; }
#pragma unroll
            for (int ks = 0; ks < 8; ++ks) {
                int abase = ((((rg << 3) + ks) * 32 + lane) << 2);
                float4 av = *(const float4*)&ma[abase];
                float4 hv4 = *(const float4*)&ha[abase];
                unsigned a0 = __float_as_uint(av.x), a1 = __float_as_uint(av.y),
                         a2 = __float_as_uint(av.z), a3 = __float_as_uint(av.w);
                unsigned h0 = __float_as_uint(hv4.x), h1 = __float_as_uint(hv4.y),
                         h2 = __float_as_uint(hv4.z), h3 = __float_as_uint(hv4.w);
                int bi_i = ((((g * 2 + ch) << 3) + ks) * 32 + lane) << 2;
                int bi_h = (((((3 + g) * 2 + ch) << 3) + ks) * 32 + lane) << 2;
                float4 wi01 = *(const float4*)&wbA[bi_i];
                float4 wi23 = *(const float4*)&wbB[bi_i];
                float4 wh01 = *(const float4*)&wbA[bi_h];
                float4 wh23 = *(const float4*)&wbB[bi_h];
                mma_tf32(ai[0], a0, a1, a2, a3, __float_as_uint(wi01.x), __float_as_uint(wi01.y));
                mma_tf32(ai[1], a0, a1, a2, a3, __float_as_uint(wi01.z), __float_as_uint(wi01.w));
                mma_tf32(ai[2], a0, a1, a2, a3, __float_as_uint(wi23.x), __float_as_uint(wi23.y));
                mma_tf32(ai[3], a0, a1, a2, a3, __float_as_uint(wi23.z), __float_as_uint(wi23.w));
                mma_tf32(ah[0], h0, h1, h2, h3, __float_as_uint(wh01.x), __float_as_uint(wh01.y));
                mma_tf32(ah[1], h0, h1, h2, h3, __float_as_uint(wh01.z), __float_as_uint(wh01.w));
                mma_tf32(ah[2], h0, h1, h2, h3, __float_as_uint(wh23.x), __float_as_uint(wh23.y));
                mma_tf32(ah[3], h0, h1, h2, h3, __float_as_uint(wh23.z), __float_as_uint(wh23.w));
            }

            if (g == 2) __syncthreads();  // all ma reads done before nh overwrite

#pragma unroll
            for (int nt = 0; nt < 4; ++nt) {
#pragma unroll
                for (int half = 0; half < 2; ++half) {  // e pairs (0,1) and (2,3)
                    int e0 = half * 2;
                    int c0 = colh + nt * 8 + (lane & 3) * 2;
                    int r = row0 + half * 8;
                    if (g == 0) {
                        rr[nt][e0]     = sigmoidf_(ai[nt][e0] + b_ih[c0] +
                                                   ah[nt][e0] + b_hh[c0]);
                        rr[nt][e0 + 1] = sigmoidf_(ai[nt][e0 + 1] + b_ih[c0 + 1] +
                                                   ah[nt][e0 + 1] + b_hh[c0 + 1]);
                    } else if (g == 1) {
                        zz[nt][e0]     = sigmoidf_(ai[nt][e0] + b_ih[64 + c0] +
                                                   ah[nt][e0] + b_hh[64 + c0]);
                        zz[nt][e0 + 1] = sigmoidf_(ai[nt][e0 + 1] + b_ih[64 + c0 + 1] +
                                                   ah[nt][e0 + 1] + b_hh[64 + c0 + 1]);
                    } else {
                        int lA = (lane >> 2) * 4;
                        float v[2];
#pragma unroll
                        for (int q = 0; q < 2; ++q) {
                            int c = c0 + q;
                            float gi = ai[nt][e0 + q] + b_ih[128 + c];
                            float gh = ah[nt][e0 + q] + b_hh[128 + c];
                            float ng = tanhf(gi + rr[nt][e0 + q] * gh);
                            int l = lA + (c & 3);
                            int j = half | (((c >> 2) & 1) << 1);
                            int pi = (((((rg) << 3) + (c >> 3)) * 32 + l) << 2) | j;
                            float hv = ha[pi];
                            v[q] = (1.f - zz[nt][e0 + q]) * ng + zz[nt][e0 + q] * hv;
                            ma[pi] = __uint_as_float(f2tf(v[q]));  // nh packed
                        }
                        int node = n0 + r;
                        if (node < NNODES)
                            *(float2*)&out[(size_t)NNODES * 64 + (size_t)node * 64 + c0] =
                                make_float2(v[0], v[1]);
                    }
                }
            }
        }
        __syncthreads();  // nh complete

        // output projection: source = nh @ Wout + bout
        float C[4][4];
#pragma unroll
        for (int nt = 0; nt < 4; ++nt)
#pragma unroll
            for (int e = 0; e < 4; ++e) C[nt][e] = 0.f;
#pragma unroll
        for (int ks = 0; ks < 8; ++ks) {
            int abase = ((((rg << 3) + ks) * 32 + lane) << 2);
            float4 av = *(const float4*)&ma[abase];
            unsigned a0 = __float_as_uint(av.x), a1 = __float_as_uint(av.y),
                     a2 = __float_as_uint(av.z), a3 = __float_as_uint(av.w);
            int bi = ((((6 * 2 + ch) << 3) + ks) * 32 + lane) << 2;
            float4 b01 = *(const float4*)&wbA[bi];
            float4 b23 = *(const float4*)&wbB[bi];
            mma_tf32(C[0], a0, a1, a2, a3, __float_as_uint(b01.x), __float_as_uint(b01.y));
            mma_tf32(C[1], a0, a1, a2, a3, __float_as_uint(b01.z), __float_as_uint(b01.w));
            mma_tf32(C[2], a0, a1, a2, a3, __float_as_uint(b23.x), __float_as_uint(b23.y));
            mma_tf32(C[3], a0, a1, a2, a3, __float_as_uint(b23.z), __float_as_uint(b23.w));
        }
#pragma unroll
        for (int nt = 0; nt < 4; ++nt) {
            int c0 = colh + nt * 8 + (lane & 3) * 2;
            float ba = bout[c0], bb = bout[c0 + 1];
            if (node0 < NNODES)
                *(float2*)&out[(size_t)node0 * 64 + c0] =
                    make_float2(C[nt][0] + ba, C[nt][1] + bb);
            if (node1 < NNODES)
                *(float2*)&out[(size_t)node1 * 64 + c0] =
                    make_float2(C[nt][2] + ba, C[nt][3] + bb);
        }
    }
}

// ---------------- launch ---------------------------------------------------
extern "C" void kernel_launch(void* const* d_in, const int* in_sizes, int n_in,
                              void* d_out, int out_size) {
    const float* x    = (const float*)d_in[0];
    const float* hin  = (const float*)d_in[1];
    const int*   srcp = (const int*)d_in[2];
    const float* Wm   = (const float*)d_in[4];
    const float* bm   = (const float*)d_in[5];
    const float* Wg   = (const float*)d_in[6];
    const float* bg   = (const float*)d_in[7];
    const float* Wfc  = (const float*)d_in[8];
    const float* al   = (const float*)d_in[9];
    const float* ar   = (const float*)d_in[10];
    const float* Wmg  = (const float*)d_in[11];
    const float* bmg  = (const float*)d_in[12];
    const float* Wih  = (const float*)d_in[13];
    const float* Whh  = (const float*)d_in[14];
    const float* bih  = (const float*)d_in[15];
    const float* bhh  = (const float*)d_in[16];
    const float* Wo   = (const float*)d_in[17];
    const float* bo   = (const float*)d_in[18];
    float* out = (float*)d_out;

    cudaFuncSetAttribute(k1_node_linear, cudaFuncAttributeMaxDynamicSharedMemorySize, K1_SMEM);
    cudaFuncSetAttribute(k3_fused, cudaFuncAttributeMaxDynamicSharedMemorySize, K3_SMEM);

    k0_fold_attn<<<1, 128>>>(Wfc, al, ar);
    k0_fold_U<<<dim3(128, 2), 64>>>(Wfc, Wmg);
    k1_node_linear<<<GRID_P, 512, K1_SMEM>>>(x, Wm, bm, Wg, Wmg);
    k2_aggregate<<<(NNODES + 7) / 8, 256>>>(srcp, Wg, bg);
    k3_fused<<<GRID_P, 512, K3_SMEM>>>(bmg, hin, Wih, Whh, bih, bhh, Wo, bo, out);
}

// round 14
// speedup vs baseline: 1.3054x; 1.0527x over previous
#include <cuda_runtime.h>
#include <cuda_fp16.h>
#include <math.h>

#define NNODES 50000
#define DEGC 16
// record (104 float words = 416B): y[128 half] | z[64 half] | el[2] er[2] xg2[2] xg1[2] (fp32)
#define RECS 104
#define NT128 391   // 128-node tiles
#define GRID_P 148

// ---------------- scratch (device globals) ---------------------------------
__device__ float g_rec[NNODES * RECS];
__device__ float g_gy[NNODES * 64];
__device__ float g_xm[NNODES * 64];
__device__ float g_vlr[128 * 4];
__device__ float g_U[2 * 128 * 64];

__device__ __forceinline__ float sigmoidf_(float v) { return 1.f / (1.f + __expf(-v)); }

__device__ __forceinline__ unsigned f2tf(float v) {
    unsigned r;
    asm("cvt.rna.tf32.f32 %0, %1;" : "=r"(r) : "f"(v));
    return r;
}

__device__ __forceinline__ void mma_tf32(float c[4], unsigned a0, unsigned a1,
                                         unsigned a2, unsigned a3,
                                         unsigned b0, unsigned b1) {
    asm volatile(
        "mma.sync.aligned.m16n8k8.row.col.f32.tf32.tf32.f32 "
        "{%0,%1,%2,%3}, {%4,%5,%6,%7}, {%8,%9}, {%0,%1,%2,%3};"
        : "+f"(c[0]), "+f"(c[1]), "+f"(c[2]), "+f"(c[3])
        : "r"(a0), "r"(a1), "r"(a2), "r"(a3), "r"(b0), "r"(b1));
}

// k1 smem (floats): wbA 16384 | wbB 16384 | wsc 1024 | xa 16384 -> 50176 = 200704 B
#define K1_WBA 0
#define K1_WBB 16384
#define K1_WSC 32768
#define K1_XA  33792
#define K1_SMEM (50176 * 4)
// k3 smem (floats): wbA 14336 | wbB 14336 | ma 8192 | ha 8192 -> 45056 = 180224 B
#define K3_WBA 0
#define K3_WBB 14336
#define K3_MA  28672
#define K3_HA  36864
#define K3_SMEM (45056 * 4)

// ---------------- K0: fold attn vectors + U (one parallel kernel) ----------
__global__ void k0_prep(const float* __restrict__ Wfc,
                        const float* __restrict__ al,
                        const float* __restrict__ ar,
                        const float* __restrict__ Wmerge) {
    int b = blockIdx.x;
    int t = threadIdx.x;  // 64
    if (b < 256) {
        int k = b & 127, h = b >> 7, c = t;
        float s = 0.f;
#pragma unroll 8
        for (int q = 0; q < 64; ++q)
            s += Wfc[k * 128 + h * 64 + q] * Wmerge[(128 + h * 64 + q) * 64 + c];
        g_U[(h * 128 + k) * 64 + c] = s;
    } else {
        for (int o = t; o < 512; o += 64) {
            int k = o >> 2, c = o & 3;
            int h = c & 1;
            const float* av = (c < 2) ? al : ar;
            float s = 0.f;
#pragma unroll 8
            for (int q = 0; q < 64; ++q)
                s += Wfc[k * 128 + h * 64 + q] * av[h * 64 + q];
            g_vlr[o] = s;
        }
    }
}

// ---------------- K1 persistent, fragment-packed smem ----------------------
__global__ __launch_bounds__(512) void k1_node_linear(
    const float* __restrict__ x, const float* __restrict__ Wm,
    const float* __restrict__ bm, const float* __restrict__ Wg,
    const float* __restrict__ Wmerge) {
    extern __shared__ float sm[];
    float* wbA = sm + K1_WBA;
    float* wbB = sm + K1_WBB;
    float* wsc = sm + K1_WSC;
    float* xa  = sm + K1_XA;
    const int tid = threadIdx.x, lane = tid & 31, wid = tid >> 5;
    const int rg = wid >> 1;           // rowgroup 0..7
    const int ch = wid & 1;            // column half
    const int row0 = rg * 16 + (lane >> 2);
    const int colh = ch * 32;

    // ---- pack weights (once): value w(p,k,c) -> fragment layout ----
    for (int idx = tid; idx < 4 * 128 * 64; idx += 512) {
        int p = idx >> 13, rem = idx & 8191, k = rem >> 6, c = rem & 63;
        float w;
        if (p == 0) w = Wm[k * 64 + c];
        else if (p == 3) w = Wmerge[k * 64 + c];
        else w = g_U[((p - 1) * 128 + k) * 64 + c];
        int l = (c & 7) * 4 + (k & 3);
        int pi = ((((p * 2 + (c >> 5)) * 16 + (k >> 3)) * 32 + l) << 2)
                 + ((c >> 3) & 1) * 2 + ((k >> 2) & 1);
        if ((c >> 4) & 1) wbB[pi] = __uint_as_float(f2tf(w));
        else              wbA[pi] = __uint_as_float(f2tf(w));
    }
    // scalar tile weights: 8 cols per k: el0,el1,er0,er1,xg2_0,xg2_1,xg1_0,xg1_1
    for (int idx = tid; idx < 128 * 8; idx += 512) {
        int k = idx >> 3, c = idx & 7;
        float v;
        if (c < 4) v = g_vlr[k * 4 + c];
        else if (c < 6) v = Wg[(128 + k) * 2 + (c - 4)];
        else v = Wg[k * 2 + (c - 6)];
        int l = c * 4 + (k & 3);
        int pi = (((k >> 3) * 32 + l) << 1) + ((k >> 2) & 1);
        wsc[pi] = __uint_as_float(f2tf(v));
    }

    for (int t = blockIdx.x; t < NT128; t += GRID_P) {
        const int n0 = t * 128;
        __syncthreads();  // prior readers done / weights packed
        for (int idx = tid; idx < 128 * 128; idx += 512) {
            int nn = idx >> 7, k = idx & 127;
            int node = n0 + nn;
            float v = (node < NNODES) ? x[node * 128 + k] : 0.f;
            int l = ((nn & 7) << 2) | (k & 3);
            int j = ((nn >> 3) & 1) | (((k >> 2) & 1) << 1);
            int pi = (((((nn >> 4) << 4) + (k >> 3)) * 32 + l) << 2) | j;
            xa[pi] = __uint_as_float(f2tf(v));
        }
        __syncthreads();

        float C[4][4][4];   // [pass][nt][e]
        float Cs[4];
#pragma unroll
        for (int p = 0; p < 4; ++p)
#pragma unroll
            for (int nt = 0; nt < 4; ++nt)
#pragma unroll
                for (int e = 0; e < 4; ++e) C[p][nt][e] = 0.f;
#pragma unroll
        for (int e = 0; e < 4; ++e) Cs[e] = 0.f;

#pragma unroll
        for (int ks = 0; ks < 16; ++ks) {
            float4 av = *(const float4*)&xa[(((rg << 4) + ks) * 32 + lane) << 2];
            unsigned a0 = __float_as_uint(av.x), a1 = __float_as_uint(av.y),
                     a2 = __float_as_uint(av.z), a3 = __float_as_uint(av.w);
#pragma unroll
            for (int p = 0; p < 4; ++p) {
                int bi = ((((p * 2 + ch) << 4) + ks) * 32 + lane) << 2;
                float4 b01 = *(const float4*)&wbA[bi];
                float4 b23 = *(const float4*)&wbB[bi];
                mma_tf32(C[p][0], a0, a1, a2, a3,
                         __float_as_uint(b01.x), __float_as_uint(b01.y));
                mma_tf32(C[p][1], a0, a1, a2, a3,
                         __float_as_uint(b01.z), __float_as_uint(b01.w));
                mma_tf32(C[p][2], a0, a1, a2, a3,
                         __float_as_uint(b23.x), __float_as_uint(b23.y));
                mma_tf32(C[p][3], a0, a1, a2, a3,
                         __float_as_uint(b23.z), __float_as_uint(b23.w));
            }
            if (ch == 0) {
                float2 sb = *(const float2*)&wsc[((ks * 32 + lane) << 1)];
                mma_tf32(Cs, a0, a1, a2, a3,
                         __float_as_uint(sb.x), __float_as_uint(sb.y));
            }
        }

        const int node0 = n0 + row0, node1 = node0 + 8;
        // p=0: z -> fp16 halves at word offset 64
#pragma unroll
        for (int nt = 0; nt < 4; ++nt) {
            int c0 = colh + nt * 8 + (lane & 3) * 2;
            float ba = bm[c0], bb = bm[c0 + 1];
            if (node0 < NNODES)
                ((__half2*)(g_rec + (size_t)node0 * RECS + 64))[c0 >> 1] =
                    __floats2half2_rn(C[0][nt][0] + ba, C[0][nt][1] + bb);
            if (node1 < NNODES)
                ((__half2*)(g_rec + (size_t)node1 * RECS + 64))[c0 >> 1] =
                    __floats2half2_rn(C[0][nt][2] + ba, C[0][nt][3] + bb);
        }
        // p=1,2: y -> fp16 halves at word offset 0 (head p-1 -> halves (p-1)*64 + c)
#pragma unroll
        for (int p = 1; p <= 2; ++p) {
#pragma unroll
            for (int nt = 0; nt < 4; ++nt) {
                int c0 = colh + nt * 8 + (lane & 3) * 2;
                int hb = (p - 1) * 64 + c0;
                if (node0 < NNODES)
                    ((__half2*)(g_rec + (size_t)node0 * RECS))[hb >> 1] =
                        __floats2half2_rn(C[p][nt][0], C[p][nt][1]);
                if (node1 < NNODES)
                    ((__half2*)(g_rec + (size_t)node1 * RECS))[hb >> 1] =
                        __floats2half2_rn(C[p][nt][2], C[p][nt][3]);
            }
        }
        // p=3: xm (fp32)
#pragma unroll
        for (int nt = 0; nt < 4; ++nt) {
            int c0 = colh + nt * 8 + (lane & 3) * 2;
            if (node0 < NNODES)
                *(float2*)&g_xm[(size_t)node0 * 64 + c0] =
                    make_float2(C[3][nt][0], C[3][nt][1]);
            if (node1 < NNODES)
                *(float2*)&g_xm[(size_t)node1 * 64 + c0] =
                    make_float2(C[3][nt][2], C[3][nt][3]);
        }
        // scalars (fp32) at word offset 96
        if (ch == 0) {
            int c0 = (lane & 3) * 2;
            if (node0 < NNODES)
                *(float2*)&g_rec[(size_t)node0 * RECS + 96 + c0] =
                    make_float2(Cs[0], Cs[1]);
            if (node1 < NNODES)
                *(float2*)&g_rec[(size_t)node1 * RECS + 96 + c0] =
                    make_float2(Cs[2], Cs[3]);
        }
    }
}

// ---------------- K2: one warp per node, fp16 gathers ----------------------
__global__ __launch_bounds__(256) void k2_aggregate(
    const int* __restrict__ src, const float* __restrict__ Wg,
    const float* __restrict__ bg) {
    const unsigned FULL = 0xffffffffu;
    const int n = blockIdx.x * 8 + ((threadIdx.x) >> 5);
    if (n >= NNODES) return;
    const int lane = threadIdx.x & 31;
    const int j16 = lane & 15, h = lane >> 4;

    int srcj = src[n * DEGC + j16];

    // e + softmax per head (16-lane butterfly groups)
    float el = g_rec[(size_t)srcj * RECS + 96 + h];
    float er = g_rec[(size_t)n * RECS + 98 + h];
    float e = el + er;
    e = (e > 0.f) ? e : 0.2f * e;
    float m = e;
#pragma unroll
    for (int o = 8; o > 0; o >>= 1) m = fmaxf(m, __shfl_xor_sync(FULL, m, o));
    float ee = __expf(e - m);
    float s = ee;
#pragma unroll
    for (int o = 8; o > 0; o >>= 1) s += __shfl_xor_sync(FULL, s, o);
    float alpha = ee / fmaxf(s, 1e-12f);

    float xg2 = g_rec[(size_t)srcj * RECS + 100 + h];
#pragma unroll
    for (int o = 8; o > 0; o >>= 1) xg2 += __shfl_xor_sync(FULL, xg2, o);

    // z max (fp16): lane owns z cols 2*lane, 2*lane+1 -> word 64+lane
    float mz0 = -3.4e38f, mz1 = -3.4e38f;
#pragma unroll
    for (int j = 0; j < 16; ++j) {
        int sj = __shfl_sync(FULL, srcj, j);
        unsigned zv = *(const unsigned*)(g_rec + (size_t)sj * RECS + 64 + lane);
        float2 z2 = __half22float2(*(__half2*)&zv);
        mz0 = fmaxf(mz0, z2.x);
        mz1 = fmaxf(mz1, z2.y);
    }
    float p0 = mz0 * Wg[(256 + 2 * lane) * 2 + 0] + mz1 * Wg[(256 + 2 * lane + 1) * 2 + 0];
    float p1 = mz0 * Wg[(256 + 2 * lane) * 2 + 1] + mz1 * Wg[(256 + 2 * lane + 1) * 2 + 1];
#pragma unroll
    for (int o = 16; o > 0; o >>= 1) {
        p0 += __shfl_xor_sync(FULL, p0, o);
        p1 += __shfl_xor_sync(FULL, p1, o);
    }
    float g3 = (h == 0) ? p0 : p1;
    float xg1 = g_rec[(size_t)n * RECS + 102 + h];
    float gate = sigmoidf_(xg1 + 0.0625f * xg2 + g3 + bg[h]);

    // alpha-weighted y (fp16): lane owns cols 4L..4L+3 -> words 2L..2L+1
    float4 acc = make_float4(0.f, 0.f, 0.f, 0.f);
#pragma unroll
    for (int j = 0; j < 16; ++j) {
        int sj = __shfl_sync(FULL, srcj, j);
        float a = __shfl_sync(FULL, alpha, (lane & 16) | j);
        uint2 yv = *(const uint2*)(g_rec + (size_t)sj * RECS + 2 * lane);
        float2 f0 = __half22float2(*(__half2*)&yv.x);
        float2 f1 = __half22float2(*(__half2*)&yv.y);
        acc.x += a * f0.x; acc.y += a * f0.y;
        acc.z += a * f1.x; acc.w += a * f1.y;
    }

    float got = __shfl_xor_sync(FULL, gate, 16);
    float ox = __shfl_xor_sync(FULL, acc.x, 16);
    float oy = __shfl_xor_sync(FULL, acc.y, 16);
    float oz = __shfl_xor_sync(FULL, acc.z, 16);
    float ow = __shfl_xor_sync(FULL, acc.w, 16);
    if (lane < 16) {
        float4 gy;
        gy.x = gate * acc.x + got * ox;
        gy.y = gate * acc.y + got * oy;
        gy.z = gate * acc.z + got * oz;
        gy.w = gate * acc.w + got * ow;
        *(float4*)&g_gy[(size_t)n * 64 + 4 * lane] = gy;
    }
}

// ---------------- K3 persistent, fragment-packed smem ----------------------
__global__ __launch_bounds__(512) void k3_fused(
    const float* __restrict__ bmerge,
    const float* __restrict__ hin, const float* __restrict__ W_ih,
    const float* __restrict__ W_hh, const float* __restrict__ b_ih,
    const float* __restrict__ b_hh, const float* __restrict__ Wout,
    const float* __restrict__ bout, float* __restrict__ out) {
    extern __shared__ float sm[];
    float* wbA = sm + K3_WBA;
    float* wbB = sm + K3_WBB;
    float* ma  = sm + K3_MA;   // meso packed; aliased by nh after g==2 (fenced)
    float* ha  = sm + K3_HA;   // hidden packed (fp32)
    const int tid = threadIdx.x, lane = tid & 31, wid = tid >> 5;
    const int rg = wid >> 1;
    const int ch = wid & 1;
    const int row0 = rg * 16 + (lane >> 2);
    const int colh = ch * 32;

    // ---- pack 7 weight matrices: 0..2 W_ih, 3..5 W_hh, 6 Wout ----
    for (int idx = tid; idx < 7 * 64 * 64; idx += 512) {
        int mm = idx >> 12, rem = idx & 4095, k = rem >> 6, c = rem & 63;
        float w;
        if (mm < 3) w = W_ih[(mm * 64 + c) * 64 + k];
        else if (mm < 6) w = W_hh[((mm - 3) * 64 + c) * 64 + k];
        else w = Wout[k * 64 + c];
        int l = (c & 7) * 4 + (k & 3);
        int pi = ((((mm * 2 + (c >> 5)) << 3) + (k >> 3)) * 32 + l) * 4
                 + ((c >> 3) & 1) * 2 + ((k >> 2) & 1);
        if ((c >> 4) & 1) wbB[pi] = __uint_as_float(f2tf(w));
        else              wbA[pi] = __uint_as_float(f2tf(w));
    }

    for (int t = blockIdx.x; t < NT128; t += GRID_P) {
        const int n0 = t * 128;
        const int node0 = n0 + row0, node1 = node0 + 8;
        __syncthreads();  // prior tile readers done / weights packed

        // fill ms (= xm + gy + bmerge, tf32) and h tile, fragment-packed
        for (int idx = tid; idx < 128 * 64; idx += 512) {
            int nn = idx >> 6, k = idx & 63;
            int node = n0 + nn;
            float mv = 0.f, hv = 0.f;
            if (node < NNODES) {
                mv = g_xm[(size_t)node * 64 + k] + g_gy[(size_t)node * 64 + k] + bmerge[k];
                hv = hin[node * 64 + k];
            }
            int l = ((nn & 7) << 2) | (k & 3);
            int j = ((nn >> 3) & 1) | (((k >> 2) & 1) << 1);
            int pi = (((((nn >> 4) << 3) + (k >> 3)) * 32 + l) << 2) | j;
            ma[pi] = __uint_as_float(f2tf(mv));
            ha[pi] = hv;
        }
        __syncthreads();

        float rr[4][4], zz[4][4];
#pragma unroll
        for (int g = 0; g < 3; ++g) {
            float ai[4][4], ah[4][4];
#pragma unroll
            for (int nt = 0; nt < 4; ++nt)
#pragma unroll
                for (int e = 0; e < 4; ++e) { ai[nt][e] = 0.f; ah[nt][e] = 0.f; }
#pragma unroll
            for (int ks = 0; ks < 8; ++ks) {
                int abase = ((((rg << 3) + ks) * 32 + lane) << 2);
                float4 av = *(const float4*)&ma[abase];
                float4 hv4 = *(const float4*)&ha[abase];
                unsigned a0 = __float_as_uint(av.x), a1 = __float_as_uint(av.y),
                         a2 = __float_as_uint(av.z), a3 = __float_as_uint(av.w);
                unsigned h0 = __float_as_uint(hv4.x), h1 = __float_as_uint(hv4.y),
                         h2 = __float_as_uint(hv4.z), h3 = __float_as_uint(hv4.w);
                int bi_i = ((((g * 2 + ch) << 3) + ks) * 32 + lane) << 2;
                int bi_h = (((((3 + g) * 2 + ch) << 3) + ks) * 32 + lane) << 2;
                float4 wi01 = *(const float4*)&wbA[bi_i];
                float4 wi23 = *(const float4*)&wbB[bi_i];
                float4 wh01 = *(const float4*)&wbA[bi_h];
                float4 wh23 = *(const float4*)&wbB[bi_h];
                mma_tf32(ai[0], a0, a1, a2, a3, __float_as_uint(wi01.x), __float_as_uint(wi01.y));
                mma_tf32(ai[1], a0, a1, a2, a3, __float_as_uint(wi01.z), __float_as_uint(wi01.w));
                mma_tf32(ai[2], a0, a1, a2, a3, __float_as_uint(wi23.x), __float_as_uint(wi23.y));
                mma_tf32(ai[3], a0, a1, a2, a3, __float_as_uint(wi23.z), __float_as_uint(wi23.w));
                mma_tf32(ah[0], h0, h1, h2, h3, __float_as_uint(wh01.x), __float_as_uint(wh01.y));
                mma_tf32(ah[1], h0, h1, h2, h3, __float_as_uint(wh01.z), __float_as_uint(wh01.w));
                mma_tf32(ah[2], h0, h1, h2, h3, __float_as_uint(wh23.x), __float_as_uint(wh23.y));
                mma_tf32(ah[3], h0, h1, h2, h3, __float_as_uint(wh23.z), __float_as_uint(wh23.w));
            }

            if (g == 2) __syncthreads();  // all ma reads done before nh overwrite

#pragma unroll
            for (int nt = 0; nt < 4; ++nt) {
#pragma unroll
                for (int half = 0; half < 2; ++half) {
                    int e0 = half * 2;
                    int c0 = colh + nt * 8 + (lane & 3) * 2;
                    int r = row0 + half * 8;
                    if (g == 0) {
                        rr[nt][e0]     = sigmoidf_(ai[nt][e0] + b_ih[c0] +
                                                   ah[nt][e0] + b_hh[c0]);
                        rr[nt][e0 + 1] = sigmoidf_(ai[nt][e0 + 1] + b_ih[c0 + 1] +
                                                   ah[nt][e0 + 1] + b_hh[c0 + 1]);
                    } else if (g == 1) {
                        zz[nt][e0]     = sigmoidf_(ai[nt][e0] + b_ih[64 + c0] +
                                                   ah[nt][e0] + b_hh[64 + c0]);
                        zz[nt][e0 + 1] = sigmoidf_(ai[nt][e0 + 1] + b_ih[64 + c0 + 1] +
                                                   ah[nt][e0 + 1] + b_hh[64 + c0 + 1]);
                    } else {
                        int lA = (lane >> 2) * 4;
                        float v[2];
#pragma unroll
                        for (int q = 0; q < 2; ++q) {
                            int c = c0 + q;
                            float gi = ai[nt][e0 + q] + b_ih[128 + c];
                            float gh = ah[nt][e0 + q] + b_hh[128 + c];
                            float ng = tanhf(gi + rr[nt][e0 + q] * gh);
                            int l = lA + (c & 3);
                            int j = half | (((c >> 2) & 1) << 1);
                            int pi = (((((rg) << 3) + (c >> 3)) * 32 + l) << 2) | j;
                            float hv = ha[pi];
                            v[q] = (1.f - zz[nt][e0 + q]) * ng + zz[nt][e0 + q] * hv;
                            ma[pi] = __uint_as_float(f2tf(v[q]));  // nh packed
                        }
                        int node = n0 + r;
                        if (node < NNODES)
                            *(float2*)&out[(size_t)NNODES * 64 + (size_t)node * 64 + c0] =
                                make_float2(v[0], v[1]);
                    }
                }
            }
        }
        __syncthreads();  // nh complete

        // output projection: source = nh @ Wout + bout
        float C[4][4];
#pragma unroll
        for (int nt = 0; nt < 4; ++nt)
#pragma unroll
            for (int e = 0; e < 4; ++e) C[nt][e] = 0.f;
#pragma unroll
        for (int ks = 0; ks < 8; ++ks) {
            int abase = ((((rg << 3) + ks) * 32 + lane) << 2);
            float4 av = *(const float4*)&ma[abase];
            unsigned a0 = __float_as_uint(av.x), a1 = __float_as_uint(av.y),
                     a2 = __float_as_uint(av.z), a3 = __float_as_uint(av.w);
            int bi = ((((6 * 2 + ch) << 3) + ks) * 32 + lane) << 2;
            float4 b01 = *(const float4*)&wbA[bi];
            float4 b23 = *(const float4*)&wbB[bi];
            mma_tf32(C[0], a0, a1, a2, a3, __float_as_uint(b01.x), __float_as_uint(b01.y));
            mma_tf32(C[1], a0, a1, a2, a3, __float_as_uint(b01.z), __float_as_uint(b01.w));
            mma_tf32(C[2], a0, a1, a2, a3, __float_as_uint(b23.x), __float_as_uint(b23.y));
            mma_tf32(C[3], a0, a1, a2, a3, __float_as_uint(b23.z), __float_as_uint(b23.w));
        }
#pragma unroll
        for (int nt = 0; nt < 4; ++nt) {
            int c0 = colh + nt * 8 + (lane & 3) * 2;
            float ba = bout[c0], bb = bout[c0 + 1];
            if (node0 < NNODES)
                *(float2*)&out[(size_t)node0 * 64 + c0] =
                    make_float2(C[nt][0] + ba, C[nt][1] + bb);
            if (node1 < NNODES)
                *(float2*)&out[(size_t)node1 * 64 + c0] =
                    make_float2(C[nt][2] + ba, C[nt][3] + bb);
        }
    }
}

// ---------------- launch ---------------------------------------------------
extern "C" void kernel_launch(void* const* d_in, const int* in_sizes, int n_in,
                              void* d_out, int out_size) {
    const float* x    = (const float*)d_in[0];
    const float* hin  = (const float*)d_in[1];
    const int*   srcp = (const int*)d_in[2];
    const float* Wm   = (const float*)d_in[4];
    const float* bm   = (const float*)d_in[5];
    const float* Wg   = (const float*)d_in[6];
    const float* bg   = (const float*)d_in[7];
    const float* Wfc  = (const float*)d_in[8];
    const float* al   = (const float*)d_in[9];
    const float* ar   = (const float*)d_in[10];
    const float* Wmg  = (const float*)d_in[11];
    const float* bmg  = (const float*)d_in[12];
    const float* Wih  = (const float*)d_in[13];
    const float* Whh  = (const float*)d_in[14];
    const float* bih  = (const float*)d_in[15];
    const float* bhh  = (const float*)d_in[16];
    const float* Wo   = (const float*)d_in[17];
    const float* bo   = (const float*)d_in[18];
    float* out = (float*)d_out;

    cudaFuncSetAttribute(k1_node_linear, cudaFuncAttributeMaxDynamicSharedMemorySize, K1_SMEM);
    cudaFuncSetAttribute(k3_fused, cudaFuncAttributeMaxDynamicSharedMemorySize, K3_SMEM);

    k0_prep<<<257, 64>>>(Wfc, al, ar, Wmg);
    k1_node_linear<<<GRID_P, 512, K1_SMEM>>>(x, Wm, bm, Wg, Wmg);
    k2_aggregate<<<(NNODES + 7) / 8, 256>>>(srcp, Wg, bg);
    k3_fused<<<GRID_P, 512, K3_SMEM>>>(bmg, hin, Wih, Whh, bih, bhh, Wo, bo, out);
}